// round 12
// baseline (speedup 1.0000x reference)
#include <cuda_runtime.h>
#include <cuda_bf16.h>
#include <cstdint>
#include <math.h>

// Problem constants
#define NV 5
#define NB_ 32      // batch
#define NP 20
#define NJ 17
#define NBONES 16
#define ND 128
#define HR 1024
#define HID 1024
#define NROWS (NB_*NP)          // 640
#define NC (NJ + NBONES)        // 33
#define NKS 7                   // k-steps of 16 (K=112)
#define NMT 32                  // m-steps of 32 h
#define XROW 240                // X row stride in bytes (56 kpairs = 224B + pad)
#define XBYTES (128 * XROW)     // 30720
#define AFRAG  (NKS * 4 * 32 * 16)          // 14336
#define ACHUNK (AFRAG + 32 * 16)            // + meta {bc1,w0,w1,w2} = 14848
#define SMEM_DYN (2 * XBYTES)               // 61440; A ring (4*ACHUNK) reuses it
#define PLANE (NC * ND)                     // 4224

// Scratch (device globals; no runtime allocation)
__device__ float g_xin[NROWS * PLANE];                       // (n, c, t)
__device__ __align__(16) unsigned char g_Wst[NMT * ACHUNK];  // A frags + meta

// ---------------------------------------------------------------------------
// helpers
// ---------------------------------------------------------------------------
__device__ __forceinline__ void split_pack(float v0, float v1, uint32_t& hi, uint32_t& lo) {
    __nv_bfloat16 h0 = __float2bfloat16(v0);
    __nv_bfloat16 h1 = __float2bfloat16(v1);
    float r0 = v0 - __bfloat162float(h0);
    float r1 = v1 - __bfloat162float(h1);
    __nv_bfloat16 l0 = __float2bfloat16(r0);
    __nv_bfloat16 l1 = __float2bfloat16(r1);
    hi = ((uint32_t)__bfloat16_as_ushort(h1) << 16) | (uint32_t)__bfloat16_as_ushort(h0);
    lo = ((uint32_t)__bfloat16_as_ushort(l1) << 16) | (uint32_t)__bfloat16_as_ushort(l0);
}

__device__ __forceinline__ uint32_t smem_u32(const void* p) {
    uint32_t a;
    asm("{ .reg .u64 t; cvta.to.shared.u64 t, %1; cvt.u32.u64 %0, t; }" : "=r"(a) : "l"(p));
    return a;
}

__device__ __forceinline__ void mma_bf16(float* c,
                                         uint32_t a0, uint32_t a1, uint32_t a2, uint32_t a3,
                                         uint32_t b0, uint32_t b1) {
    asm volatile("mma.sync.aligned.m16n8k16.row.col.f32.bf16.bf16.f32 "
                 "{%0,%1,%2,%3},{%4,%5,%6,%7},{%8,%9},{%0,%1,%2,%3};"
                 : "+f"(c[0]), "+f"(c[1]), "+f"(c[2]), "+f"(c[3])
                 : "r"(a0), "r"(a1), "r"(a2), "r"(a3), "r"(b0), "r"(b1));
}

__device__ __forceinline__ void ldsm4(uint32_t* r, uint32_t addr) {
    asm volatile("ldmatrix.sync.aligned.m8n8.x4.shared.b16 {%0,%1,%2,%3}, [%4];"
                 : "=r"(r[0]), "=r"(r[1]), "=r"(r[2]), "=r"(r[3]) : "r"(addr));
}

__device__ __forceinline__ void cp16(uint32_t s, const void* g) {
    asm volatile("cp.async.cg.shared.global [%0], [%1], 16;" :: "r"(s), "l"(g));
}
__device__ __forceinline__ void cp_commit() { asm volatile("cp.async.commit_group;" ::: "memory"); }
__device__ __forceinline__ void cp_wait2()  { asm volatile("cp.async.wait_group 2;" ::: "memory"); }
__device__ __forceinline__ void cp_wait1()  { asm volatile("cp.async.wait_group 1;" ::: "memory"); }
__device__ __forceinline__ void cp_wait0()  { asm volatile("cp.async.wait_group 0;" ::: "memory"); }

__device__ __forceinline__ float fsqrt_ap(float x) {
    float r; asm("sqrt.approx.f32 %0, %1;" : "=f"(r) : "f"(x)); return r;
}

// ---------------------------------------------------------------------------
// Kernel W: pack conv1 weights into per-mt A-fragment chunks + meta.
// ---------------------------------------------------------------------------
__global__ __launch_bounds__(256) void k_repack_frag(
    const float* __restrict__ Wc1, const float* __restrict__ bc1,
    const float* __restrict__ Wc2)
{
    const int mt  = blockIdx.x;
    const int tid = threadIdx.x;
    unsigned char* chunk = g_Wst + (size_t)mt * ACHUNK;

    if (tid < 224) {
        const int ks = tid >> 5, lane = tid & 31;
        const int g = lane >> 2, q = lane & 3;
        const int k0 = ks * 16 + 2 * q;
        #pragma unroll
        for (int tile = 0; tile < 2; ++tile) {
            const int hA = mt * 32 + tile * 16 + g;
            const int hB = hA + 8;
            const int hh[4] = {hA, hB, hA, hB};
            const int kk[4] = {k0, k0, k0 + 8, k0 + 8};
            float v[8];
            #pragma unroll
            for (int r = 0; r < 4; ++r) {
                v[2*r]   = (kk[r]     < 99) ? Wc1[hh[r] * 99 + kk[r]]     : 0.0f;
                v[2*r+1] = (kk[r] + 1 < 99) ? Wc1[hh[r] * 99 + kk[r] + 1] : 0.0f;
            }
            uint32_t hi[4], lo[4];
            #pragma unroll
            for (int r = 0; r < 4; ++r) split_pack(v[2*r], v[2*r+1], hi[r], lo[r]);
            *(uint4*)(chunk + (((ks * 4 + 0 + tile) * 32) + lane) * 16) =
                make_uint4(hi[0], hi[1], hi[2], hi[3]);
            *(uint4*)(chunk + (((ks * 4 + 2 + tile) * 32) + lane) * 16) =
                make_uint4(lo[0], lo[1], lo[2], lo[3]);
        }
    } else {
        const int hl = tid - 224;
        const int h = mt * 32 + hl;
        *(float4*)(chunk + AFRAG + hl * 16) =
            make_float4(bc1[h], Wc2[h * 3], Wc2[h * 3 + 1], Wc2[h * 3 + 2]);
    }
}

// ---------------------------------------------------------------------------
// Kernel B: rough MLP + projection + matching + scores (all fused).
// One block per (b,p); thread = depth bin d.  (R9 structure; argmin with
// 4-way ILP; bone table hardcoded -> px/py register-resident, no s_p2t.)
// ---------------------------------------------------------------------------
__global__ __launch_bounds__(128) void k_match(
    const float* __restrict__ kpts, const float* __restrict__ joint_vis,
    const float* __restrict__ cam_R, const float* __restrict__ cam_T,
    const float* __restrict__ cam_f, const float* __restrict__ cam_c,
    const float* __restrict__ image_wh, const int* __restrict__ num_persons,
    const float* __restrict__ Wr1, const float* __restrict__ br1,
    const float* __restrict__ Wr2, const float* __restrict__ br2)
{
    __shared__ float xs[NJ * 2];
    __shared__ float hs[HR];
    __shared__ float s_rough[NJ];
    __shared__ float s_uvn[NJ * 2];
    __shared__ float s_R0[9], s_T0[3];
    __shared__ float s_pr[NP * NJ * 2];
    __shared__ float s_vr[NP * NJ];
    __shared__ float s_Rr[9], s_Tr[3], s_fr[2], s_cr[2], s_wh[2];
    __shared__ float4 s_q4[NP * NJ];
    __shared__ float s_base[NP], s_den[NP];

    const int n = blockIdx.x;
    const int b = n / NP, p = n % NP;
    const int d = threadIdx.x;

    // ---- static loads + rough-MLP input ----
    if (d < NJ * 2)
        xs[d] = kpts[(((0 * NB_ + b) * NP + p) * NJ) * 2 + d] / image_wh[d & 1];
    if (d < 9)  s_R0[d] = cam_R[(0 * NB_ + b) * 9 + d];
    if (d < 3)  s_T0[d] = cam_T[(0 * NB_ + b) * 3 + d];
    if (d >= 64 && d < 64 + NJ * 2) {
        int m = d - 64;
        int c = m & 1;
        float cc = cam_c[(0 * NB_ + b) * 2 + c];
        float ff = cam_f[(0 * NB_ + b) * 2 + c];
        s_uvn[m] = (kpts[(((0 * NB_ + b) * NP + p) * NJ) * 2 + m] - cc) / ff;
    }
    __syncthreads();

    // ---- rough MLP (fused) ----
    for (int i = d; i < HR; i += 128) {
        const float* wr = Wr1 + i * (NJ * 2);
        float acc = br1[i];
        #pragma unroll
        for (int m = 0; m < NJ * 2; ++m) acc += wr[m] * xs[m];
        hs[i] = fmaxf(acc, 0.0f);
    }
    __syncthreads();
    {
        const int warp = d >> 5, lane = d & 31;
        for (int j = warp; j < NJ; j += 4) {
            const float* wr = Wr2 + j * HR;
            float acc = 0.0f;
            for (int i = lane; i < HR; i += 32) acc += hs[i] * wr[i];
            #pragma unroll
            for (int off = 16; off > 0; off >>= 1)
                acc += __shfl_down_sync(0xffffffffu, acc, off);
            if (lane == 0) s_rough[j] = (acc + br2[j]) * 1000.0f;
        }
    }

    float sc[NJ], bd[NJ], sc2[NBONES], bd2[NBONES];
    #pragma unroll
    for (int j = 0; j < NJ; ++j) { sc[j] = 0.0f; bd[j] = 0.0f; }
    #pragma unroll
    for (int e = 0; e < NBONES; ++e) { sc2[e] = 0.0f; bd2[e] = 0.0f; }

    const float label = ((float)d / 127.0f) * 6000.0f + 2000.0f;
    const int ba[NBONES]  = {0,0,1,2,5,5,7,6,8,5,6,11,11,13,12,14};
    const int bbt[NBONES] = {1,2,3,4,6,7,9,8,10,11,12,12,13,15,14,16};

    for (int rv = 1; rv < NV; ++rv) {
        __syncthreads();
        const int cambase = rv * NB_ + b;
        {
            const float* src = kpts + (size_t)cambase * NP * NJ * 2;
            for (int idx = d; idx < NP * NJ * 2; idx += 128) s_pr[idx] = src[idx];
            const float* vsrc = joint_vis + (size_t)cambase * NP * NJ;
            for (int idx = d; idx < NP * NJ; idx += 128) s_vr[idx] = vsrc[idx];
            if (d < 9) s_Rr[d] = cam_R[cambase * 9 + d];
            if (d < 3) s_Tr[d] = cam_T[cambase * 3 + d];
            if (d < 2) {
                s_fr[d] = cam_f[cambase * 2 + d];
                s_cr[d] = cam_c[cambase * 2 + d];
                s_wh[d] = image_wh[cambase * 2 + d];
            }
        }
        __syncthreads();
        // per-view precompute for expanded-distance argmin
        for (int idx = d; idx < NP * NJ; idx += 128) {
            float w   = s_vr[idx];
            float prx = s_pr[2 * idx];
            float pry = s_pr[2 * idx + 1];
            s_q4[idx] = make_float4(w, 2.0f * w * prx, 2.0f * w * pry,
                                    w * (prx * prx + pry * pry));
        }
        __syncthreads();
        if (d < NP) {
            float bs = 0.0f, dn = 0.0f;
            #pragma unroll
            for (int j = 0; j < NJ; ++j) {
                bs += s_q4[d * NJ + j].w;
                dn += s_q4[d * NJ + j].x;
            }
            s_base[d] = bs; s_den[d] = dn;
        }
        __syncthreads();
        const int np_r = num_persons[rv * NB_ + b];

        // ---- projection ----
        float px[NJ], py[NJ], s2[NJ];
        #pragma unroll
        for (int j = 0; j < NJ; ++j) {
            float z  = label + s_rough[j];
            float cx = s_uvn[2 * j] * z;
            float cy = s_uvn[2 * j + 1] * z;
            float p0 = s_R0[0] * cx + s_R0[3] * cy + s_R0[6] * z + s_T0[0];
            float p1 = s_R0[1] * cx + s_R0[4] * cy + s_R0[7] * z + s_T0[1];
            float p2 = s_R0[2] * cx + s_R0[5] * cy + s_R0[8] * z + s_T0[2];
            float q0 = p0 - s_Tr[0], q1 = p1 - s_Tr[1], q2 = p2 - s_Tr[2];
            float xc0 = s_Rr[0] * q0 + s_Rr[1] * q1 + s_Rr[2] * q2;
            float xc1 = s_Rr[3] * q0 + s_Rr[4] * q1 + s_Rr[5] * q2;
            float xc2 = s_Rr[6] * q0 + s_Rr[7] * q1 + s_Rr[8] * q2;
            float inv = 1.0f / (xc2 + 1e-8f);
            px[j] = xc0 * inv * s_fr[0] + s_cr[0];
            py[j] = xc1 * inv * s_fr[1] + s_cr[1];
            s2[j] = px[j] * px[j] + py[j] * py[j];
        }

        // ---- argmin via expanded distance, 4 independent accumulators ----
        float best = 3.4e38f; int mm = 0;
        for (int q = 0; q < NP; ++q) {
            const float4* fq = s_q4 + q * NJ;
            float n0 = s_base[q], n1 = 0.0f, n2 = 0.0f, n3 = 0.0f;
            #pragma unroll
            for (int j = 0; j < 16; j += 4) {
                float4 f0 = fq[j],     f1 = fq[j + 1];
                float4 f2 = fq[j + 2], f3 = fq[j + 3];
                n0 = fmaf(f0.x, s2[j],     n0);
                n0 = fmaf(-f0.y, px[j],    n0);
                n0 = fmaf(-f0.z, py[j],    n0);
                n1 = fmaf(f1.x, s2[j + 1], n1);
                n1 = fmaf(-f1.y, px[j + 1], n1);
                n1 = fmaf(-f1.z, py[j + 1], n1);
                n2 = fmaf(f2.x, s2[j + 2], n2);
                n2 = fmaf(-f2.y, px[j + 2], n2);
                n2 = fmaf(-f2.z, py[j + 2], n2);
                n3 = fmaf(f3.x, s2[j + 3], n3);
                n3 = fmaf(-f3.y, px[j + 3], n3);
                n3 = fmaf(-f3.z, py[j + 3], n3);
            }
            {
                float4 f = fq[16];
                n1 = fmaf(f.x, s2[16], n1);
                n2 = fmaf(-f.y, px[16], n2);
                n3 = fmaf(-f.z, py[16], n3);
            }
            float num = (n0 + n1) + (n2 + n3);
            float val = __fdividef(num, s_den[q] + 1e-8f);
            if (q >= np_r) val = 100000.0f;
            if (val < best) { best = val; mm = q; }
        }

        // ---- scores ----
        const int mbase = mm * NJ;
        #pragma unroll
        for (int j = 0; j < NJ; ++j) {
            float mx = s_pr[(mbase + j) * 2];
            float my = s_pr[(mbase + j) * 2 + 1];
            float mv = s_vr[mbase + j];
            float dx = px[j] - mx, dy = py[j] - my;
            float score = __expf(-fsqrt_ap(dx * dx + dy * dy + 1e-12f) * 0.01f);
            float inb = (px[j] >= 0.0f && py[j] >= 0.0f &&
                         px[j] <= s_wh[0] - 1.0f && py[j] <= s_wh[1] - 1.0f) ? 1.0f : 0.0f;
            float bnd = inb * mv;
            sc[j] += score * bnd;
            bd[j] += bnd;
        }

        // ---- bone scores (hardcoded table; px/py register-resident) ----
        const float b20 = s_vr[mbase + 0];
        #pragma unroll
        for (int e = 0; e < NBONES; ++e) {
            const int a = ba[e], bb = bbt[e];
            float dxp = px[a] - px[bb], dyp = py[a] - py[bb];
            float blp = fsqrt_ap(dxp * dxp + dyp * dyp + 1e-12f);
            float max_ = s_pr[(mbase + a) * 2],  may_ = s_pr[(mbase + a) * 2 + 1];
            float mbx_ = s_pr[(mbase + bb) * 2], mby_ = s_pr[(mbase + bb) * 2 + 1];
            float dxm = max_ - mbx_, dym = may_ - mby_;
            float blm = fsqrt_ap(dxm * dxm + dym * dym + 1e-12f);
            float sbl = __expf(-fabsf(blm - blp) * 0.2f);
            sc2[e] += sbl * b20;
            bd2[e] += b20;
        }
    }

    float* xrow = g_xin + (size_t)n * PLANE;
    #pragma unroll
    for (int j = 0; j < NJ; ++j)
        xrow[j * ND + d] = sc[j] / (bd[j] + 1e-8f);
    #pragma unroll
    for (int e = 0; e < NBONES; ++e)
        xrow[(NJ + e) * ND + d] = sc2[e] / (bd2[e] + 1e-8f);
}

// ---------------------------------------------------------------------------
// Kernel C: conv1 bf16-split GEMM (mma.sync, 2 CTA/SM) + register-resident
// conv2 + softmax + masked expectation.  (unchanged from R9)
// ---------------------------------------------------------------------------
__global__ __launch_bounds__(256, 2) void k_conv_tc(
    const float* __restrict__ bc2, float* __restrict__ out)
{
    extern __shared__ __align__(16) unsigned char smem_raw[];
    __shared__ float sER[8], sEL[8];
    __shared__ float s_logit[ND];
    __shared__ float s_red[ND];

    const int n   = blockIdx.x;
    const int tid = threadIdx.x;
    const int w    = tid >> 5;
    const int lane = tid & 31;
    const int g = lane >> 2, q = lane & 3;

    const uint32_t sbase = smem_u32(smem_raw);
    const uint32_t xhi = sbase;
    const uint32_t xlo = sbase + XBYTES;

    // ---- build im2col X (t-major, bf16 hi/lo k-pairs) ----
    {
        const float* src = g_xin + (size_t)n * PLANE;
        for (int idx = tid; idx < 128 * 64; idx += 256) {
            const int kp = idx & 63;
            if (kp >= 56) continue;
            const int t = idx >> 6;
            const int k0 = 2 * kp;
            float v0 = 0.0f, v1 = 0.0f;
            if (k0 < 99) {
                int c = k0 / 3, tap = k0 - 3 * c;
                int tt = t + tap - 1;
                if (tt >= 0 && tt < ND) v0 = src[c * ND + tt];
            }
            if (k0 + 1 < 99) {
                int c = (k0 + 1) / 3, tap = (k0 + 1) - 3 * c;
                int tt = t + tap - 1;
                if (tt >= 0 && tt < ND) v1 = src[c * ND + tt];
            }
            uint32_t hi, lo;
            split_pack(v0, v1, hi, lo);
            const uint32_t off = (uint32_t)t * XROW + (uint32_t)kp * 4;
            asm volatile("st.shared.b32 [%0], %1;" :: "r"(xhi + off), "r"(hi) : "memory");
            asm volatile("st.shared.b32 [%0], %1;" :: "r"(xlo + off), "r"(lo) : "memory");
        }
    }
    __syncthreads();   // X visible

    // ---- load resident B fragments (all 7 k-steps for this warp's 16 t) ----
    uint32_t bh[NKS][4], bl[NKS][4];
    {
        const int seg = lane >> 3, rs = lane & 7;
        const int t = 16 * w + ((seg & 2) << 2) + rs;   // +8 rows for seg 2,3
        const uint32_t kbyte = (uint32_t)(seg & 1) * 16u;
        #pragma unroll
        for (int ks = 0; ks < NKS; ++ks) {
            const uint32_t a = xhi + (uint32_t)t * XROW + (uint32_t)ks * 32 + kbyte;
            ldsm4(bh[ks], a);
            ldsm4(bl[ks], a + XBYTES);
        }
    }
    __syncthreads();   // all ldsm done -> X region reusable as A ring

    // ---- prologue: chunks 0,1,2 into ring slots 0,1,2 ----
    #pragma unroll
    for (int c = 0; c < 3; ++c) {
        const unsigned char* gsrc = g_Wst + (size_t)c * ACHUNK;
        const uint32_t dst = sbase + (uint32_t)(c * ACHUNK);
        for (int i = tid; i < ACHUNK / 16; i += 256) cp16(dst + i * 16, gsrc + i * 16);
        cp_commit();
    }

    float P0 = 0.0f, P1 = 0.0f, P2 = 0.0f, P3 = 0.0f, eR = 0.0f, eL = 0.0f;

    #pragma unroll 1
    for (int mt = 0; mt < NMT; ++mt) {
        if (mt < NMT - 2) cp_wait2();
        else if (mt == NMT - 2) cp_wait1();
        else cp_wait0();
        __syncthreads();   // chunk mt resident; slot (mt+3)&3 readers done

        if (mt + 3 < NMT) {
            const unsigned char* gsrc = g_Wst + (size_t)(mt + 3) * ACHUNK;
            const uint32_t dst = sbase + (uint32_t)(((mt + 3) & 3) * ACHUNK);
            for (int i = tid; i < ACHUNK / 16; i += 256) cp16(dst + i * 16, gsrc + i * 16);
            cp_commit();
        }

        const uint4* sA = (const uint4*)(smem_raw + (mt & 3) * ACHUNK);

        float acc0[2][4], acc1[2][4];
        #pragma unroll
        for (int nt = 0; nt < 2; ++nt)
            #pragma unroll
            for (int j = 0; j < 4; ++j) { acc0[nt][j] = 0.0f; acc1[nt][j] = 0.0f; }

        #pragma unroll
        for (int ks = 0; ks < NKS; ++ks) {
            const uint4 h0 = sA[(ks * 4 + 0) * 32 + lane];
            const uint4 h1 = sA[(ks * 4 + 1) * 32 + lane];
            const uint4 l0 = sA[(ks * 4 + 2) * 32 + lane];
            const uint4 l1 = sA[(ks * 4 + 3) * 32 + lane];
            #pragma unroll
            for (int nt = 0; nt < 2; ++nt) {
                const uint32_t b0h = bh[ks][2 * nt], b1h = bh[ks][2 * nt + 1];
                const uint32_t b0l = bl[ks][2 * nt], b1l = bl[ks][2 * nt + 1];
                mma_bf16(acc0[nt], h0.x, h0.y, h0.z, h0.w, b0h, b1h);
                mma_bf16(acc0[nt], h0.x, h0.y, h0.z, h0.w, b0l, b1l);
                mma_bf16(acc0[nt], l0.x, l0.y, l0.z, l0.w, b0h, b1h);
                mma_bf16(acc1[nt], h1.x, h1.y, h1.z, h1.w, b0h, b1h);
                mma_bf16(acc1[nt], h1.x, h1.y, h1.z, h1.w, b0l, b1l);
                mma_bf16(acc1[nt], l1.x, l1.y, l1.z, l1.w, b0h, b1h);
            }
        }

        // ---- fused conv2 epilogue: 4 h-rows per lane (g, g+8, g+16, g+24) ----
        const float4* meta = (const float4*)(smem_raw + (mt & 3) * ACHUNK + AFRAG);
        #pragma unroll
        for (int r = 0; r < 4; ++r) {
            const float4 m = meta[g + 8 * r];
            float ya, yb, yc, yd;
            if (r == 0)      { ya = acc0[0][0]; yb = acc0[0][1]; yc = acc0[1][0]; yd = acc0[1][1]; }
            else if (r == 1) { ya = acc0[0][2]; yb = acc0[0][3]; yc = acc0[1][2]; yd = acc0[1][3]; }
            else if (r == 2) { ya = acc1[0][0]; yb = acc1[0][1]; yc = acc1[1][0]; yd = acc1[1][1]; }
            else             { ya = acc1[0][2]; yb = acc1[0][3]; yc = acc1[1][2]; yd = acc1[1][3]; }
            ya = fmaxf(ya + m.x, 0.0f);
            yb = fmaxf(yb + m.x, 0.0f);
            yc = fmaxf(yc + m.x, 0.0f);
            yd = fmaxf(yd + m.x, 0.0f);
            const float w0 = m.y, w1 = m.z, w2 = m.w;

            const float n_b = __shfl_sync(0xffffffffu, yb, lane - 1);  // y[2q-1]
            const float n_a = __shfl_sync(0xffffffffu, ya, lane + 1);  // y[2q+2]
            const float n_d = __shfl_sync(0xffffffffu, yd, lane - 1);  // y[2q+7]
            const float n_c = __shfl_sync(0xffffffffu, yc, lane + 1);  // y[2q+10]
            const float x_b = __shfl_sync(0xffffffffu, yb, lane | 3);  // y[7]
            const float x_c = __shfl_sync(0xffffffffu, yc, lane & ~3); // y[8]

            P0 += w1 * ya + w2 * yb + ((q > 0) ? w0 * n_b : 0.0f);
            P1 += w0 * ya + w1 * yb + w2 * ((q < 3) ? n_a : x_c);
            P2 += w1 * yc + w2 * yd + w0 * ((q > 0) ? n_d : x_b);
            P3 += w0 * yc + w1 * yd + ((q < 3) ? w2 * n_c : 0.0f);
            if (q == 3) eR += w0 * yd;   // -> logit[16w+16]
            if (q == 0) eL += w2 * ya;   // -> logit[16w-1]
        }
    }

    // ---- reduce P over g (lane bits 2..4) ----
    #pragma unroll
    for (int off = 4; off <= 16; off <<= 1) {
        P0 += __shfl_xor_sync(0xffffffffu, P0, off);
        P1 += __shfl_xor_sync(0xffffffffu, P1, off);
        P2 += __shfl_xor_sync(0xffffffffu, P2, off);
        P3 += __shfl_xor_sync(0xffffffffu, P3, off);
    }
    #pragma unroll
    for (int off = 1; off <= 16; off <<= 1) {
        eR += __shfl_xor_sync(0xffffffffu, eR, off);
        eL += __shfl_xor_sync(0xffffffffu, eL, off);
    }
    if (lane < 4) {
        s_logit[16 * w + 2 * lane]     = P0;
        s_logit[16 * w + 2 * lane + 1] = P1;
        s_logit[16 * w + 2 * lane + 8] = P2;
        s_logit[16 * w + 2 * lane + 9] = P3;
    }
    if (lane == 0) { sER[w] = eR; sEL[w] = eL; }
    __syncthreads();

    if (tid < ND) {
        const int wt = tid >> 4, lt = tid & 15;
        float v = s_logit[tid] + bc2[0];
        if (lt == 0  && wt > 0) v += sER[wt - 1];
        if (lt == 15 && wt < 7) v += sEL[wt + 1];
        s_logit[tid] = v;
    }
    __syncthreads();

    // ---- softmax + argmax window + masked expectation ----
    if (tid < ND) s_red[tid] = s_logit[tid];
    __syncthreads();
    for (int s = 64; s > 0; s >>= 1) {
        if (tid < s) s_red[tid] = fmaxf(s_red[tid], s_red[tid + s]);
        __syncthreads();
    }
    const float mx = s_red[0];
    __syncthreads();

    if (tid < ND) s_red[tid] = (s_logit[tid] == mx) ? (float)tid : 1.0e9f;
    __syncthreads();
    for (int s = 64; s > 0; s >>= 1) {
        if (tid < s) s_red[tid] = fminf(s_red[tid], s_red[tid + s]);
        __syncthreads();
    }
    const int idx = (int)s_red[0];
    __syncthreads();

    float e = 0.0f;
    if (tid < ND) e = expf(s_logit[tid] - mx);

    if (tid < ND) s_red[tid] = e;
    __syncthreads();
    for (int s = 64; s > 0; s >>= 1) {
        if (tid < s) s_red[tid] += s_red[tid + s];
        __syncthreads();
    }
    const float S = s_red[0];
    __syncthreads();

    const float me = (tid < ND && abs(tid - idx) <= 5) ? e : 0.0f;

    if (tid < ND) s_red[tid] = me;
    __syncthreads();
    for (int s = 64; s > 0; s >>= 1) {
        if (tid < s) s_red[tid] += s_red[tid + s];
        __syncthreads();
    }
    const float den = s_red[0];
    __syncthreads();

    if (tid < ND) s_red[tid] = me * (float)tid;
    __syncthreads();
    for (int s = 64; s > 0; s >>= 1) {
        if (tid < s) s_red[tid] += s_red[tid + s];
        __syncthreads();
    }
    if (tid == 0) {
        float pred = s_red[0] / (den + 1e-8f * S);
        out[n] = pred * (6000.0f / 127.0f) + 2000.0f;
    }
}

// ---------------------------------------------------------------------------
extern "C" void kernel_launch(void* const* d_in, const int* in_sizes, int n_in,
                              void* d_out, int out_size)
{
    const float* kpts        = (const float*)d_in[0];
    const float* joint_vis   = (const float*)d_in[2];
    const float* cam_R       = (const float*)d_in[5];
    const float* cam_T       = (const float*)d_in[6];
    const float* cam_f       = (const float*)d_in[7];
    const float* cam_c       = (const float*)d_in[8];
    const float* image_wh    = (const float*)d_in[9];
    const int*   num_persons = (const int*)d_in[10];
    const float* Wr1         = (const float*)d_in[11];
    const float* br1         = (const float*)d_in[12];
    const float* Wr2         = (const float*)d_in[13];
    const float* br2         = (const float*)d_in[14];
    const float* Wc1         = (const float*)d_in[15];
    const float* bc1         = (const float*)d_in[16];
    const float* Wc2         = (const float*)d_in[17];
    const float* bc2         = (const float*)d_in[18];
    float* out = (float*)d_out;

    cudaFuncSetAttribute(k_conv_tc, cudaFuncAttributeMaxDynamicSharedMemorySize,
                         SMEM_DYN);

    k_repack_frag<<<NMT, 256>>>(Wc1, bc1, Wc2);
    k_match<<<NROWS, 128>>>(kpts, joint_vis, cam_R, cam_T, cam_f, cam_c,
                            image_wh, num_persons, Wr1, br1, Wr2, br2);
    k_conv_tc<<<NROWS, 256, SMEM_DYN>>>(bc2, out);
}

// round 13
// speedup vs baseline: 1.1359x; 1.1359x over previous
#include <cuda_runtime.h>
#include <cuda_bf16.h>
#include <cstdint>
#include <math.h>

// Problem constants
#define NV 5
#define NB_ 32      // batch
#define NP 20
#define NJ 17
#define NBONES 16
#define ND 128
#define HR 1024
#define HID 1024
#define NROWS (NB_*NP)          // 640
#define NC (NJ + NBONES)        // 33
#define NKS 7                   // k-steps of 16 (K=112)
#define NMT 32                  // m-steps of 32 h
#define XROW 240                // X row stride in bytes (56 kpairs = 224B + pad)
#define XBYTES (128 * XROW)     // 30720
#define AFRAG  (NKS * 4 * 32 * 16)          // 14336
#define ACHUNK (AFRAG + 32 * 16)            // + meta {bc1,w0,w1,w2} = 14848
#define SMEM_DYN (2 * XBYTES)               // 61440; A ring (4*ACHUNK) reuses it
#define PLANE (NC * ND)                     // 4224

// Scratch (device globals; no runtime allocation)
__device__ float g_xin[NROWS * PLANE];                       // (n, c, t)
__device__ __align__(16) unsigned char g_Wst[NMT * ACHUNK];  // A frags + meta

// ---------------------------------------------------------------------------
// helpers
// ---------------------------------------------------------------------------
__device__ __forceinline__ void split_pack(float v0, float v1, uint32_t& hi, uint32_t& lo) {
    __nv_bfloat16 h0 = __float2bfloat16(v0);
    __nv_bfloat16 h1 = __float2bfloat16(v1);
    float r0 = v0 - __bfloat162float(h0);
    float r1 = v1 - __bfloat162float(h1);
    __nv_bfloat16 l0 = __float2bfloat16(r0);
    __nv_bfloat16 l1 = __float2bfloat16(r1);
    hi = ((uint32_t)__bfloat16_as_ushort(h1) << 16) | (uint32_t)__bfloat16_as_ushort(h0);
    lo = ((uint32_t)__bfloat16_as_ushort(l1) << 16) | (uint32_t)__bfloat16_as_ushort(l0);
}

__device__ __forceinline__ uint32_t smem_u32(const void* p) {
    uint32_t a;
    asm("{ .reg .u64 t; cvta.to.shared.u64 t, %1; cvt.u32.u64 %0, t; }" : "=r"(a) : "l"(p));
    return a;
}

__device__ __forceinline__ void mma_bf16(float* c,
                                         uint32_t a0, uint32_t a1, uint32_t a2, uint32_t a3,
                                         uint32_t b0, uint32_t b1) {
    asm volatile("mma.sync.aligned.m16n8k16.row.col.f32.bf16.bf16.f32 "
                 "{%0,%1,%2,%3},{%4,%5,%6,%7},{%8,%9},{%0,%1,%2,%3};"
                 : "+f"(c[0]), "+f"(c[1]), "+f"(c[2]), "+f"(c[3])
                 : "r"(a0), "r"(a1), "r"(a2), "r"(a3), "r"(b0), "r"(b1));
}

__device__ __forceinline__ void ldsm4(uint32_t* r, uint32_t addr) {
    asm volatile("ldmatrix.sync.aligned.m8n8.x4.shared.b16 {%0,%1,%2,%3}, [%4];"
                 : "=r"(r[0]), "=r"(r[1]), "=r"(r[2]), "=r"(r[3]) : "r"(addr));
}

__device__ __forceinline__ void cp16(uint32_t s, const void* g) {
    asm volatile("cp.async.cg.shared.global [%0], [%1], 16;" :: "r"(s), "l"(g));
}
__device__ __forceinline__ void cp_commit() { asm volatile("cp.async.commit_group;" ::: "memory"); }
__device__ __forceinline__ void cp_wait2()  { asm volatile("cp.async.wait_group 2;" ::: "memory"); }
__device__ __forceinline__ void cp_wait1()  { asm volatile("cp.async.wait_group 1;" ::: "memory"); }
__device__ __forceinline__ void cp_wait0()  { asm volatile("cp.async.wait_group 0;" ::: "memory"); }

__device__ __forceinline__ float fsqrt_ap(float x) {
    float r; asm("sqrt.approx.f32 %0, %1;" : "=f"(r) : "f"(x)); return r;
}

// ---------------------------------------------------------------------------
// Kernel W: pack conv1 weights into per-mt A-fragment chunks + meta.
// ---------------------------------------------------------------------------
__global__ __launch_bounds__(256) void k_repack_frag(
    const float* __restrict__ Wc1, const float* __restrict__ bc1,
    const float* __restrict__ Wc2)
{
    const int mt  = blockIdx.x;
    const int tid = threadIdx.x;
    unsigned char* chunk = g_Wst + (size_t)mt * ACHUNK;

    if (tid < 224) {
        const int ks = tid >> 5, lane = tid & 31;
        const int g = lane >> 2, q = lane & 3;
        const int k0 = ks * 16 + 2 * q;
        #pragma unroll
        for (int tile = 0; tile < 2; ++tile) {
            const int hA = mt * 32 + tile * 16 + g;
            const int hB = hA + 8;
            const int hh[4] = {hA, hB, hA, hB};
            const int kk[4] = {k0, k0, k0 + 8, k0 + 8};
            float v[8];
            #pragma unroll
            for (int r = 0; r < 4; ++r) {
                v[2*r]   = (kk[r]     < 99) ? Wc1[hh[r] * 99 + kk[r]]     : 0.0f;
                v[2*r+1] = (kk[r] + 1 < 99) ? Wc1[hh[r] * 99 + kk[r] + 1] : 0.0f;
            }
            uint32_t hi[4], lo[4];
            #pragma unroll
            for (int r = 0; r < 4; ++r) split_pack(v[2*r], v[2*r+1], hi[r], lo[r]);
            *(uint4*)(chunk + (((ks * 4 + 0 + tile) * 32) + lane) * 16) =
                make_uint4(hi[0], hi[1], hi[2], hi[3]);
            *(uint4*)(chunk + (((ks * 4 + 2 + tile) * 32) + lane) * 16) =
                make_uint4(lo[0], lo[1], lo[2], lo[3]);
        }
    } else {
        const int hl = tid - 224;
        const int h = mt * 32 + hl;
        *(float4*)(chunk + AFRAG + hl * 16) =
            make_float4(bc1[h], Wc2[h * 3], Wc2[h * 3 + 1], Wc2[h * 3 + 2]);
    }
}

// ---------------------------------------------------------------------------
// Kernel B: rough MLP + projection + matching + scores (all fused).
// One block per (b,p); thread = depth bin d.  (R9 structure; float2 LDS.)
// ---------------------------------------------------------------------------
__global__ __launch_bounds__(128) void k_match(
    const float* __restrict__ kpts, const float* __restrict__ joint_vis,
    const float* __restrict__ cam_R, const float* __restrict__ cam_T,
    const float* __restrict__ cam_f, const float* __restrict__ cam_c,
    const float* __restrict__ image_wh, const int* __restrict__ num_persons,
    const float* __restrict__ Wr1, const float* __restrict__ br1,
    const float* __restrict__ Wr2, const float* __restrict__ br2)
{
    __shared__ float xs[NJ * 2];
    __shared__ float hs[HR];
    __shared__ float s_rough[NJ];
    __shared__ __align__(8) float s_uvn[NJ * 2];
    __shared__ float s_R0[9], s_T0[3];
    __shared__ __align__(8) float s_pr[NP * NJ * 2];
    __shared__ float s_vr[NP * NJ];
    __shared__ float s_Rr[9], s_Tr[3], s_fr[2], s_cr[2], s_wh[2];
    __shared__ float4 s_q4[NP * NJ];
    __shared__ float s_base[NP], s_den[NP];

    const int n = blockIdx.x;
    const int b = n / NP, p = n % NP;
    const int d = threadIdx.x;

    // ---- static loads + rough-MLP input ----
    if (d < NJ * 2)
        xs[d] = kpts[(((0 * NB_ + b) * NP + p) * NJ) * 2 + d] / image_wh[d & 1];
    if (d < 9)  s_R0[d] = cam_R[(0 * NB_ + b) * 9 + d];
    if (d < 3)  s_T0[d] = cam_T[(0 * NB_ + b) * 3 + d];
    if (d >= 64 && d < 64 + NJ * 2) {
        int m = d - 64;
        int c = m & 1;
        float cc = cam_c[(0 * NB_ + b) * 2 + c];
        float ff = cam_f[(0 * NB_ + b) * 2 + c];
        s_uvn[m] = (kpts[(((0 * NB_ + b) * NP + p) * NJ) * 2 + m] - cc) / ff;
    }
    __syncthreads();

    // ---- rough MLP (fused) ----
    for (int i = d; i < HR; i += 128) {
        const float* wr = Wr1 + i * (NJ * 2);
        float acc = br1[i];
        #pragma unroll
        for (int m = 0; m < NJ * 2; ++m) acc += wr[m] * xs[m];
        hs[i] = fmaxf(acc, 0.0f);
    }
    __syncthreads();
    {
        const int warp = d >> 5, lane = d & 31;
        for (int j = warp; j < NJ; j += 4) {
            const float* wr = Wr2 + j * HR;
            float acc = 0.0f;
            for (int i = lane; i < HR; i += 32) acc += hs[i] * wr[i];
            #pragma unroll
            for (int off = 16; off > 0; off >>= 1)
                acc += __shfl_down_sync(0xffffffffu, acc, off);
            if (lane == 0) s_rough[j] = (acc + br2[j]) * 1000.0f;
        }
    }

    float sc[NJ], bd[NJ], sc2[NBONES], bd2[NBONES];
    #pragma unroll
    for (int j = 0; j < NJ; ++j) { sc[j] = 0.0f; bd[j] = 0.0f; }
    #pragma unroll
    for (int e = 0; e < NBONES; ++e) { sc2[e] = 0.0f; bd2[e] = 0.0f; }

    const float label = ((float)d / 127.0f) * 6000.0f + 2000.0f;
    const int ba[NBONES]  = {0,0,1,2,5,5,7,6,8,5,6,11,11,13,12,14};
    const int bbt[NBONES] = {1,2,3,4,6,7,9,8,10,11,12,12,13,15,14,16};

    for (int rv = 1; rv < NV; ++rv) {
        __syncthreads();
        const int cambase = rv * NB_ + b;
        {
            const float* src = kpts + (size_t)cambase * NP * NJ * 2;
            for (int idx = d; idx < NP * NJ * 2; idx += 128) s_pr[idx] = src[idx];
            const float* vsrc = joint_vis + (size_t)cambase * NP * NJ;
            for (int idx = d; idx < NP * NJ; idx += 128) s_vr[idx] = vsrc[idx];
            if (d < 9) s_Rr[d] = cam_R[cambase * 9 + d];
            if (d < 3) s_Tr[d] = cam_T[cambase * 3 + d];
            if (d < 2) {
                s_fr[d] = cam_f[cambase * 2 + d];
                s_cr[d] = cam_c[cambase * 2 + d];
                s_wh[d] = image_wh[cambase * 2 + d];
            }
        }
        __syncthreads();
        // per-view precompute for expanded-distance argmin
        for (int idx = d; idx < NP * NJ; idx += 128) {
            float w   = s_vr[idx];
            float2 pr = *(const float2*)&s_pr[2 * idx];
            s_q4[idx] = make_float4(w, 2.0f * w * pr.x, 2.0f * w * pr.y,
                                    w * (pr.x * pr.x + pr.y * pr.y));
        }
        __syncthreads();
        if (d < NP) {
            float bs = 0.0f, dn = 0.0f;
            #pragma unroll
            for (int j = 0; j < NJ; ++j) {
                bs += s_q4[d * NJ + j].w;
                dn += s_q4[d * NJ + j].x;
            }
            s_base[d] = bs; s_den[d] = dn;
        }
        __syncthreads();
        const int np_r = num_persons[rv * NB_ + b];

        // ---- projection ----
        float px[NJ], py[NJ], s2[NJ];
        #pragma unroll
        for (int j = 0; j < NJ; ++j) {
            float z  = label + s_rough[j];
            float2 uv = *(const float2*)&s_uvn[2 * j];
            float cx = uv.x * z;
            float cy = uv.y * z;
            float p0 = s_R0[0] * cx + s_R0[3] * cy + s_R0[6] * z + s_T0[0];
            float p1 = s_R0[1] * cx + s_R0[4] * cy + s_R0[7] * z + s_T0[1];
            float p2 = s_R0[2] * cx + s_R0[5] * cy + s_R0[8] * z + s_T0[2];
            float q0 = p0 - s_Tr[0], q1 = p1 - s_Tr[1], q2 = p2 - s_Tr[2];
            float xc0 = s_Rr[0] * q0 + s_Rr[1] * q1 + s_Rr[2] * q2;
            float xc1 = s_Rr[3] * q0 + s_Rr[4] * q1 + s_Rr[5] * q2;
            float xc2 = s_Rr[6] * q0 + s_Rr[7] * q1 + s_Rr[8] * q2;
            float inv = 1.0f / (xc2 + 1e-8f);
            px[j] = xc0 * inv * s_fr[0] + s_cr[0];
            py[j] = xc1 * inv * s_fr[1] + s_cr[1];
            s2[j] = px[j] * px[j] + py[j] * py[j];
        }

        // ---- argmin via expanded distance (single accumulator, as R9) ----
        float best = 3.4e38f; int mm = 0;
        for (int q = 0; q < NP; ++q) {
            float num = s_base[q];
            #pragma unroll
            for (int j = 0; j < NJ; ++j) {
                float4 f = s_q4[q * NJ + j];
                num = fmaf(f.x, s2[j], num);
                num = fmaf(-f.y, px[j], num);
                num = fmaf(-f.z, py[j], num);
            }
            float val = __fdividef(num, s_den[q] + 1e-8f);
            if (q >= np_r) val = 100000.0f;
            if (val < best) { best = val; mm = q; }
        }

        // ---- scores (float2 matched-keypoint loads) ----
        const int mbase = mm * NJ;
        #pragma unroll
        for (int j = 0; j < NJ; ++j) {
            float2 mp = *(const float2*)&s_pr[2 * (mbase + j)];
            float mv = s_vr[mbase + j];
            float dx = px[j] - mp.x, dy = py[j] - mp.y;
            float score = __expf(-fsqrt_ap(dx * dx + dy * dy + 1e-12f) * 0.01f);
            float inb = (px[j] >= 0.0f && py[j] >= 0.0f &&
                         px[j] <= s_wh[0] - 1.0f && py[j] <= s_wh[1] - 1.0f) ? 1.0f : 0.0f;
            float bnd = inb * mv;
            sc[j] += score * bnd;
            bd[j] += bnd;
        }

        // ---- bone scores (hardcoded table; px/py register-resident) ----
        const float b20 = s_vr[mbase + 0];
        #pragma unroll
        for (int e = 0; e < NBONES; ++e) {
            const int a = ba[e], bb = bbt[e];
            float dxp = px[a] - px[bb], dyp = py[a] - py[bb];
            float blp = fsqrt_ap(dxp * dxp + dyp * dyp + 1e-12f);
            float2 ma = *(const float2*)&s_pr[2 * (mbase + a)];
            float2 mb = *(const float2*)&s_pr[2 * (mbase + bb)];
            float dxm = ma.x - mb.x, dym = ma.y - mb.y;
            float blm = fsqrt_ap(dxm * dxm + dym * dym + 1e-12f);
            float sbl = __expf(-fabsf(blm - blp) * 0.2f);
            sc2[e] += sbl * b20;
            bd2[e] += b20;
        }
    }

    float* xrow = g_xin + (size_t)n * PLANE;
    #pragma unroll
    for (int j = 0; j < NJ; ++j)
        xrow[j * ND + d] = sc[j] / (bd[j] + 1e-8f);
    #pragma unroll
    for (int e = 0; e < NBONES; ++e)
        xrow[(NJ + e) * ND + d] = sc2[e] / (bd2[e] + 1e-8f);
}

// ---------------------------------------------------------------------------
// Kernel C: conv1 bf16-split GEMM (mma.sync, 2 CTA/SM) + register-resident
// conv2 + softmax + masked expectation.  (unchanged from R9)
// ---------------------------------------------------------------------------
__global__ __launch_bounds__(256, 2) void k_conv_tc(
    const float* __restrict__ bc2, float* __restrict__ out)
{
    extern __shared__ __align__(16) unsigned char smem_raw[];
    __shared__ float sER[8], sEL[8];
    __shared__ float s_logit[ND];
    __shared__ float s_red[ND];

    const int n   = blockIdx.x;
    const int tid = threadIdx.x;
    const int w    = tid >> 5;
    const int lane = tid & 31;
    const int g = lane >> 2, q = lane & 3;

    const uint32_t sbase = smem_u32(smem_raw);
    const uint32_t xhi = sbase;
    const uint32_t xlo = sbase + XBYTES;

    // ---- build im2col X (t-major, bf16 hi/lo k-pairs) ----
    {
        const float* src = g_xin + (size_t)n * PLANE;
        for (int idx = tid; idx < 128 * 64; idx += 256) {
            const int kp = idx & 63;
            if (kp >= 56) continue;
            const int t = idx >> 6;
            const int k0 = 2 * kp;
            float v0 = 0.0f, v1 = 0.0f;
            if (k0 < 99) {
                int c = k0 / 3, tap = k0 - 3 * c;
                int tt = t + tap - 1;
                if (tt >= 0 && tt < ND) v0 = src[c * ND + tt];
            }
            if (k0 + 1 < 99) {
                int c = (k0 + 1) / 3, tap = (k0 + 1) - 3 * c;
                int tt = t + tap - 1;
                if (tt >= 0 && tt < ND) v1 = src[c * ND + tt];
            }
            uint32_t hi, lo;
            split_pack(v0, v1, hi, lo);
            const uint32_t off = (uint32_t)t * XROW + (uint32_t)kp * 4;
            asm volatile("st.shared.b32 [%0], %1;" :: "r"(xhi + off), "r"(hi) : "memory");
            asm volatile("st.shared.b32 [%0], %1;" :: "r"(xlo + off), "r"(lo) : "memory");
        }
    }
    __syncthreads();   // X visible

    // ---- load resident B fragments (all 7 k-steps for this warp's 16 t) ----
    uint32_t bh[NKS][4], bl[NKS][4];
    {
        const int seg = lane >> 3, rs = lane & 7;
        const int t = 16 * w + ((seg & 2) << 2) + rs;   // +8 rows for seg 2,3
        const uint32_t kbyte = (uint32_t)(seg & 1) * 16u;
        #pragma unroll
        for (int ks = 0; ks < NKS; ++ks) {
            const uint32_t a = xhi + (uint32_t)t * XROW + (uint32_t)ks * 32 + kbyte;
            ldsm4(bh[ks], a);
            ldsm4(bl[ks], a + XBYTES);
        }
    }
    __syncthreads();   // all ldsm done -> X region reusable as A ring

    // ---- prologue: chunks 0,1,2 into ring slots 0,1,2 ----
    #pragma unroll
    for (int c = 0; c < 3; ++c) {
        const unsigned char* gsrc = g_Wst + (size_t)c * ACHUNK;
        const uint32_t dst = sbase + (uint32_t)(c * ACHUNK);
        for (int i = tid; i < ACHUNK / 16; i += 256) cp16(dst + i * 16, gsrc + i * 16);
        cp_commit();
    }

    float P0 = 0.0f, P1 = 0.0f, P2 = 0.0f, P3 = 0.0f, eR = 0.0f, eL = 0.0f;

    #pragma unroll 1
    for (int mt = 0; mt < NMT; ++mt) {
        if (mt < NMT - 2) cp_wait2();
        else if (mt == NMT - 2) cp_wait1();
        else cp_wait0();
        __syncthreads();   // chunk mt resident; slot (mt+3)&3 readers done

        if (mt + 3 < NMT) {
            const unsigned char* gsrc = g_Wst + (size_t)(mt + 3) * ACHUNK;
            const uint32_t dst = sbase + (uint32_t)(((mt + 3) & 3) * ACHUNK);
            for (int i = tid; i < ACHUNK / 16; i += 256) cp16(dst + i * 16, gsrc + i * 16);
            cp_commit();
        }

        const uint4* sA = (const uint4*)(smem_raw + (mt & 3) * ACHUNK);

        float acc0[2][4], acc1[2][4];
        #pragma unroll
        for (int nt = 0; nt < 2; ++nt)
            #pragma unroll
            for (int j = 0; j < 4; ++j) { acc0[nt][j] = 0.0f; acc1[nt][j] = 0.0f; }

        #pragma unroll
        for (int ks = 0; ks < NKS; ++ks) {
            const uint4 h0 = sA[(ks * 4 + 0) * 32 + lane];
            const uint4 h1 = sA[(ks * 4 + 1) * 32 + lane];
            const uint4 l0 = sA[(ks * 4 + 2) * 32 + lane];
            const uint4 l1 = sA[(ks * 4 + 3) * 32 + lane];
            #pragma unroll
            for (int nt = 0; nt < 2; ++nt) {
                const uint32_t b0h = bh[ks][2 * nt], b1h = bh[ks][2 * nt + 1];
                const uint32_t b0l = bl[ks][2 * nt], b1l = bl[ks][2 * nt + 1];
                mma_bf16(acc0[nt], h0.x, h0.y, h0.z, h0.w, b0h, b1h);
                mma_bf16(acc0[nt], h0.x, h0.y, h0.z, h0.w, b0l, b1l);
                mma_bf16(acc0[nt], l0.x, l0.y, l0.z, l0.w, b0h, b1h);
                mma_bf16(acc1[nt], h1.x, h1.y, h1.z, h1.w, b0h, b1h);
                mma_bf16(acc1[nt], h1.x, h1.y, h1.z, h1.w, b0l, b1l);
                mma_bf16(acc1[nt], l1.x, l1.y, l1.z, l1.w, b0h, b1h);
            }
        }

        // ---- fused conv2 epilogue: 4 h-rows per lane (g, g+8, g+16, g+24) ----
        const float4* meta = (const float4*)(smem_raw + (mt & 3) * ACHUNK + AFRAG);
        #pragma unroll
        for (int r = 0; r < 4; ++r) {
            const float4 m = meta[g + 8 * r];
            float ya, yb, yc, yd;
            if (r == 0)      { ya = acc0[0][0]; yb = acc0[0][1]; yc = acc0[1][0]; yd = acc0[1][1]; }
            else if (r == 1) { ya = acc0[0][2]; yb = acc0[0][3]; yc = acc0[1][2]; yd = acc0[1][3]; }
            else if (r == 2) { ya = acc1[0][0]; yb = acc1[0][1]; yc = acc1[1][0]; yd = acc1[1][1]; }
            else             { ya = acc1[0][2]; yb = acc1[0][3]; yc = acc1[1][2]; yd = acc1[1][3]; }
            ya = fmaxf(ya + m.x, 0.0f);
            yb = fmaxf(yb + m.x, 0.0f);
            yc = fmaxf(yc + m.x, 0.0f);
            yd = fmaxf(yd + m.x, 0.0f);
            const float w0 = m.y, w1 = m.z, w2 = m.w;

            const float n_b = __shfl_sync(0xffffffffu, yb, lane - 1);  // y[2q-1]
            const float n_a = __shfl_sync(0xffffffffu, ya, lane + 1);  // y[2q+2]
            const float n_d = __shfl_sync(0xffffffffu, yd, lane - 1);  // y[2q+7]
            const float n_c = __shfl_sync(0xffffffffu, yc, lane + 1);  // y[2q+10]
            const float x_b = __shfl_sync(0xffffffffu, yb, lane | 3);  // y[7]
            const float x_c = __shfl_sync(0xffffffffu, yc, lane & ~3); // y[8]

            P0 += w1 * ya + w2 * yb + ((q > 0) ? w0 * n_b : 0.0f);
            P1 += w0 * ya + w1 * yb + w2 * ((q < 3) ? n_a : x_c);
            P2 += w1 * yc + w2 * yd + w0 * ((q > 0) ? n_d : x_b);
            P3 += w0 * yc + w1 * yd + ((q < 3) ? w2 * n_c : 0.0f);
            if (q == 3) eR += w0 * yd;   // -> logit[16w+16]
            if (q == 0) eL += w2 * ya;   // -> logit[16w-1]
        }
    }

    // ---- reduce P over g (lane bits 2..4) ----
    #pragma unroll
    for (int off = 4; off <= 16; off <<= 1) {
        P0 += __shfl_xor_sync(0xffffffffu, P0, off);
        P1 += __shfl_xor_sync(0xffffffffu, P1, off);
        P2 += __shfl_xor_sync(0xffffffffu, P2, off);
        P3 += __shfl_xor_sync(0xffffffffu, P3, off);
    }
    #pragma unroll
    for (int off = 1; off <= 16; off <<= 1) {
        eR += __shfl_xor_sync(0xffffffffu, eR, off);
        eL += __shfl_xor_sync(0xffffffffu, eL, off);
    }
    if (lane < 4) {
        s_logit[16 * w + 2 * lane]     = P0;
        s_logit[16 * w + 2 * lane + 1] = P1;
        s_logit[16 * w + 2 * lane + 8] = P2;
        s_logit[16 * w + 2 * lane + 9] = P3;
    }
    if (lane == 0) { sER[w] = eR; sEL[w] = eL; }
    __syncthreads();

    if (tid < ND) {
        const int wt = tid >> 4, lt = tid & 15;
        float v = s_logit[tid] + bc2[0];
        if (lt == 0  && wt > 0) v += sER[wt - 1];
        if (lt == 15 && wt < 7) v += sEL[wt + 1];
        s_logit[tid] = v;
    }
    __syncthreads();

    // ---- softmax + argmax window + masked expectation ----
    if (tid < ND) s_red[tid] = s_logit[tid];
    __syncthreads();
    for (int s = 64; s > 0; s >>= 1) {
        if (tid < s) s_red[tid] = fmaxf(s_red[tid], s_red[tid + s]);
        __syncthreads();
    }
    const float mx = s_red[0];
    __syncthreads();

    if (tid < ND) s_red[tid] = (s_logit[tid] == mx) ? (float)tid : 1.0e9f;
    __syncthreads();
    for (int s = 64; s > 0; s >>= 1) {
        if (tid < s) s_red[tid] = fminf(s_red[tid], s_red[tid + s]);
        __syncthreads();
    }
    const int idx = (int)s_red[0];
    __syncthreads();

    float e = 0.0f;
    if (tid < ND) e = expf(s_logit[tid] - mx);

    if (tid < ND) s_red[tid] = e;
    __syncthreads();
    for (int s = 64; s > 0; s >>= 1) {
        if (tid < s) s_red[tid] += s_red[tid + s];
        __syncthreads();
    }
    const float S = s_red[0];
    __syncthreads();

    const float me = (tid < ND && abs(tid - idx) <= 5) ? e : 0.0f;

    if (tid < ND) s_red[tid] = me;
    __syncthreads();
    for (int s = 64; s > 0; s >>= 1) {
        if (tid < s) s_red[tid] += s_red[tid + s];
        __syncthreads();
    }
    const float den = s_red[0];
    __syncthreads();

    if (tid < ND) s_red[tid] = me * (float)tid;
    __syncthreads();
    for (int s = 64; s > 0; s >>= 1) {
        if (tid < s) s_red[tid] += s_red[tid + s];
        __syncthreads();
    }
    if (tid == 0) {
        float pred = s_red[0] / (den + 1e-8f * S);
        out[n] = pred * (6000.0f / 127.0f) + 2000.0f;
    }
}

// ---------------------------------------------------------------------------
extern "C" void kernel_launch(void* const* d_in, const int* in_sizes, int n_in,
                              void* d_out, int out_size)
{
    const float* kpts        = (const float*)d_in[0];
    const float* joint_vis   = (const float*)d_in[2];
    const float* cam_R       = (const float*)d_in[5];
    const float* cam_T       = (const float*)d_in[6];
    const float* cam_f       = (const float*)d_in[7];
    const float* cam_c       = (const float*)d_in[8];
    const float* image_wh    = (const float*)d_in[9];
    const int*   num_persons = (const int*)d_in[10];
    const float* Wr1         = (const float*)d_in[11];
    const float* br1         = (const float*)d_in[12];
    const float* Wr2         = (const float*)d_in[13];
    const float* br2         = (const float*)d_in[14];
    const float* Wc1         = (const float*)d_in[15];
    const float* bc1         = (const float*)d_in[16];
    const float* Wc2         = (const float*)d_in[17];
    const float* bc2         = (const float*)d_in[18];
    float* out = (float*)d_out;

    cudaFuncSetAttribute(k_conv_tc, cudaFuncAttributeMaxDynamicSharedMemorySize,
                         SMEM_DYN);

    k_repack_frag<<<NMT, 256>>>(Wc1, bc1, Wc2);
    k_match<<<NROWS, 128>>>(kpts, joint_vis, cam_R, cam_T, cam_f, cam_c,
                            image_wh, num_persons, Wr1, br1, Wr2, br2);
    k_conv_tc<<<NROWS, 256, SMEM_DYN>>>(bc2, out);
}

// round 14
// speedup vs baseline: 1.2099x; 1.0651x over previous
#include <cuda_runtime.h>
#include <cuda_bf16.h>
#include <cstdint>
#include <math.h>

// Problem constants
#define NV 5
#define NB_ 32      // batch
#define NP 20
#define NJ 17
#define NBONES 16
#define ND 128
#define HR 1024
#define HID 1024
#define NROWS (NB_*NP)          // 640
#define NC (NJ + NBONES)        // 33
#define NKS 7                   // k-steps of 16 (K=112)
#define NMT 32                  // m-steps of 32 h
#define XROW 240                // X row stride in bytes (56 kpairs = 224B + pad)
#define XBYTES (128 * XROW)     // 30720
#define AFRAG  (NKS * 4 * 32 * 16)          // 14336
#define ACHUNK (AFRAG + 32 * 16)            // + meta {bc1,w0,w1,w2} = 14848
#define SMEM_DYN (2 * XBYTES)               // 61440; A ring (4*ACHUNK) reuses it
#define PLANE (NC * ND)                     // 4224

// Scratch (device globals; no runtime allocation)
__device__ float g_xin[NROWS * PLANE];                       // (n, c, t)
__device__ __align__(16) unsigned char g_Wst[NMT * ACHUNK];  // A frags + meta

// ---------------------------------------------------------------------------
// helpers
// ---------------------------------------------------------------------------
__device__ __forceinline__ void split_pack(float v0, float v1, uint32_t& hi, uint32_t& lo) {
    __nv_bfloat16 h0 = __float2bfloat16(v0);
    __nv_bfloat16 h1 = __float2bfloat16(v1);
    float r0 = v0 - __bfloat162float(h0);
    float r1 = v1 - __bfloat162float(h1);
    __nv_bfloat16 l0 = __float2bfloat16(r0);
    __nv_bfloat16 l1 = __float2bfloat16(r1);
    hi = ((uint32_t)__bfloat16_as_ushort(h1) << 16) | (uint32_t)__bfloat16_as_ushort(h0);
    lo = ((uint32_t)__bfloat16_as_ushort(l1) << 16) | (uint32_t)__bfloat16_as_ushort(l0);
}

__device__ __forceinline__ uint32_t smem_u32(const void* p) {
    uint32_t a;
    asm("{ .reg .u64 t; cvta.to.shared.u64 t, %1; cvt.u32.u64 %0, t; }" : "=r"(a) : "l"(p));
    return a;
}

__device__ __forceinline__ void mma_bf16(float* c,
                                         uint32_t a0, uint32_t a1, uint32_t a2, uint32_t a3,
                                         uint32_t b0, uint32_t b1) {
    asm volatile("mma.sync.aligned.m16n8k16.row.col.f32.bf16.bf16.f32 "
                 "{%0,%1,%2,%3},{%4,%5,%6,%7},{%8,%9},{%0,%1,%2,%3};"
                 : "+f"(c[0]), "+f"(c[1]), "+f"(c[2]), "+f"(c[3])
                 : "r"(a0), "r"(a1), "r"(a2), "r"(a3), "r"(b0), "r"(b1));
}

__device__ __forceinline__ void ldsm4(uint32_t* r, uint32_t addr) {
    asm volatile("ldmatrix.sync.aligned.m8n8.x4.shared.b16 {%0,%1,%2,%3}, [%4];"
                 : "=r"(r[0]), "=r"(r[1]), "=r"(r[2]), "=r"(r[3]) : "r"(addr));
}

__device__ __forceinline__ void cp16(uint32_t s, const void* g) {
    asm volatile("cp.async.cg.shared.global [%0], [%1], 16;" :: "r"(s), "l"(g));
}
__device__ __forceinline__ void cp_commit() { asm volatile("cp.async.commit_group;" ::: "memory"); }
__device__ __forceinline__ void cp_wait2()  { asm volatile("cp.async.wait_group 2;" ::: "memory"); }
__device__ __forceinline__ void cp_wait1()  { asm volatile("cp.async.wait_group 1;" ::: "memory"); }
__device__ __forceinline__ void cp_wait0()  { asm volatile("cp.async.wait_group 0;" ::: "memory"); }

__device__ __forceinline__ float fsqrt_ap(float x) {
    float r; asm("sqrt.approx.f32 %0, %1;" : "=f"(r) : "f"(x)); return r;
}

// ---------------------------------------------------------------------------
// Kernel W: pack conv1 weights into per-mt A-fragment chunks + meta.
// ---------------------------------------------------------------------------
__global__ __launch_bounds__(256) void k_repack_frag(
    const float* __restrict__ Wc1, const float* __restrict__ bc1,
    const float* __restrict__ Wc2)
{
    const int mt  = blockIdx.x;
    const int tid = threadIdx.x;
    unsigned char* chunk = g_Wst + (size_t)mt * ACHUNK;

    if (tid < 224) {
        const int ks = tid >> 5, lane = tid & 31;
        const int g = lane >> 2, q = lane & 3;
        const int k0 = ks * 16 + 2 * q;
        #pragma unroll
        for (int tile = 0; tile < 2; ++tile) {
            const int hA = mt * 32 + tile * 16 + g;
            const int hB = hA + 8;
            const int hh[4] = {hA, hB, hA, hB};
            const int kk[4] = {k0, k0, k0 + 8, k0 + 8};
            float v[8];
            #pragma unroll
            for (int r = 0; r < 4; ++r) {
                v[2*r]   = (kk[r]     < 99) ? Wc1[hh[r] * 99 + kk[r]]     : 0.0f;
                v[2*r+1] = (kk[r] + 1 < 99) ? Wc1[hh[r] * 99 + kk[r] + 1] : 0.0f;
            }
            uint32_t hi[4], lo[4];
            #pragma unroll
            for (int r = 0; r < 4; ++r) split_pack(v[2*r], v[2*r+1], hi[r], lo[r]);
            *(uint4*)(chunk + (((ks * 4 + 0 + tile) * 32) + lane) * 16) =
                make_uint4(hi[0], hi[1], hi[2], hi[3]);
            *(uint4*)(chunk + (((ks * 4 + 2 + tile) * 32) + lane) * 16) =
                make_uint4(lo[0], lo[1], lo[2], lo[3]);
        }
    } else {
        const int hl = tid - 224;
        const int h = mt * 32 + hl;
        *(float4*)(chunk + AFRAG + hl * 16) =
            make_float4(bc1[h], Wc2[h * 3], Wc2[h * 3 + 1], Wc2[h * 3 + 2]);
    }
}

// ---------------------------------------------------------------------------
// Kernel B: rough MLP + projection + matching + scores (all fused).
// One block per (b,p); thread = depth bin d.  (R13, unchanged)
// ---------------------------------------------------------------------------
__global__ __launch_bounds__(128) void k_match(
    const float* __restrict__ kpts, const float* __restrict__ joint_vis,
    const float* __restrict__ cam_R, const float* __restrict__ cam_T,
    const float* __restrict__ cam_f, const float* __restrict__ cam_c,
    const float* __restrict__ image_wh, const int* __restrict__ num_persons,
    const float* __restrict__ Wr1, const float* __restrict__ br1,
    const float* __restrict__ Wr2, const float* __restrict__ br2)
{
    __shared__ float xs[NJ * 2];
    __shared__ float hs[HR];
    __shared__ float s_rough[NJ];
    __shared__ __align__(8) float s_uvn[NJ * 2];
    __shared__ float s_R0[9], s_T0[3];
    __shared__ __align__(8) float s_pr[NP * NJ * 2];
    __shared__ float s_vr[NP * NJ];
    __shared__ float s_Rr[9], s_Tr[3], s_fr[2], s_cr[2], s_wh[2];
    __shared__ float4 s_q4[NP * NJ];
    __shared__ float s_base[NP], s_den[NP];

    const int n = blockIdx.x;
    const int b = n / NP, p = n % NP;
    const int d = threadIdx.x;

    // ---- static loads + rough-MLP input ----
    if (d < NJ * 2)
        xs[d] = kpts[(((0 * NB_ + b) * NP + p) * NJ) * 2 + d] / image_wh[d & 1];
    if (d < 9)  s_R0[d] = cam_R[(0 * NB_ + b) * 9 + d];
    if (d < 3)  s_T0[d] = cam_T[(0 * NB_ + b) * 3 + d];
    if (d >= 64 && d < 64 + NJ * 2) {
        int m = d - 64;
        int c = m & 1;
        float cc = cam_c[(0 * NB_ + b) * 2 + c];
        float ff = cam_f[(0 * NB_ + b) * 2 + c];
        s_uvn[m] = (kpts[(((0 * NB_ + b) * NP + p) * NJ) * 2 + m] - cc) / ff;
    }
    __syncthreads();

    // ---- rough MLP (fused) ----
    for (int i = d; i < HR; i += 128) {
        const float* wr = Wr1 + i * (NJ * 2);
        float acc = br1[i];
        #pragma unroll
        for (int m = 0; m < NJ * 2; ++m) acc += wr[m] * xs[m];
        hs[i] = fmaxf(acc, 0.0f);
    }
    __syncthreads();
    {
        const int warp = d >> 5, lane = d & 31;
        for (int j = warp; j < NJ; j += 4) {
            const float* wr = Wr2 + j * HR;
            float acc = 0.0f;
            for (int i = lane; i < HR; i += 32) acc += hs[i] * wr[i];
            #pragma unroll
            for (int off = 16; off > 0; off >>= 1)
                acc += __shfl_down_sync(0xffffffffu, acc, off);
            if (lane == 0) s_rough[j] = (acc + br2[j]) * 1000.0f;
        }
    }

    float sc[NJ], bd[NJ], sc2[NBONES], bd2[NBONES];
    #pragma unroll
    for (int j = 0; j < NJ; ++j) { sc[j] = 0.0f; bd[j] = 0.0f; }
    #pragma unroll
    for (int e = 0; e < NBONES; ++e) { sc2[e] = 0.0f; bd2[e] = 0.0f; }

    const float label = ((float)d / 127.0f) * 6000.0f + 2000.0f;
    const int ba[NBONES]  = {0,0,1,2,5,5,7,6,8,5,6,11,11,13,12,14};
    const int bbt[NBONES] = {1,2,3,4,6,7,9,8,10,11,12,12,13,15,14,16};

    for (int rv = 1; rv < NV; ++rv) {
        __syncthreads();
        const int cambase = rv * NB_ + b;
        {
            const float* src = kpts + (size_t)cambase * NP * NJ * 2;
            for (int idx = d; idx < NP * NJ * 2; idx += 128) s_pr[idx] = src[idx];
            const float* vsrc = joint_vis + (size_t)cambase * NP * NJ;
            for (int idx = d; idx < NP * NJ; idx += 128) s_vr[idx] = vsrc[idx];
            if (d < 9) s_Rr[d] = cam_R[cambase * 9 + d];
            if (d < 3) s_Tr[d] = cam_T[cambase * 3 + d];
            if (d < 2) {
                s_fr[d] = cam_f[cambase * 2 + d];
                s_cr[d] = cam_c[cambase * 2 + d];
                s_wh[d] = image_wh[cambase * 2 + d];
            }
        }
        __syncthreads();
        // per-view precompute for expanded-distance argmin
        for (int idx = d; idx < NP * NJ; idx += 128) {
            float w   = s_vr[idx];
            float2 pr = *(const float2*)&s_pr[2 * idx];
            s_q4[idx] = make_float4(w, 2.0f * w * pr.x, 2.0f * w * pr.y,
                                    w * (pr.x * pr.x + pr.y * pr.y));
        }
        __syncthreads();
        if (d < NP) {
            float bs = 0.0f, dn = 0.0f;
            #pragma unroll
            for (int j = 0; j < NJ; ++j) {
                bs += s_q4[d * NJ + j].w;
                dn += s_q4[d * NJ + j].x;
            }
            s_base[d] = bs; s_den[d] = dn;
        }
        __syncthreads();
        const int np_r = num_persons[rv * NB_ + b];

        // ---- projection ----
        float px[NJ], py[NJ], s2[NJ];
        #pragma unroll
        for (int j = 0; j < NJ; ++j) {
            float z  = label + s_rough[j];
            float2 uv = *(const float2*)&s_uvn[2 * j];
            float cx = uv.x * z;
            float cy = uv.y * z;
            float p0 = s_R0[0] * cx + s_R0[3] * cy + s_R0[6] * z + s_T0[0];
            float p1 = s_R0[1] * cx + s_R0[4] * cy + s_R0[7] * z + s_T0[1];
            float p2 = s_R0[2] * cx + s_R0[5] * cy + s_R0[8] * z + s_T0[2];
            float q0 = p0 - s_Tr[0], q1 = p1 - s_Tr[1], q2 = p2 - s_Tr[2];
            float xc0 = s_Rr[0] * q0 + s_Rr[1] * q1 + s_Rr[2] * q2;
            float xc1 = s_Rr[3] * q0 + s_Rr[4] * q1 + s_Rr[5] * q2;
            float xc2 = s_Rr[6] * q0 + s_Rr[7] * q1 + s_Rr[8] * q2;
            float inv = 1.0f / (xc2 + 1e-8f);
            px[j] = xc0 * inv * s_fr[0] + s_cr[0];
            py[j] = xc1 * inv * s_fr[1] + s_cr[1];
            s2[j] = px[j] * px[j] + py[j] * py[j];
        }

        // ---- argmin via expanded distance (single accumulator) ----
        float best = 3.4e38f; int mm = 0;
        for (int q = 0; q < NP; ++q) {
            float num = s_base[q];
            #pragma unroll
            for (int j = 0; j < NJ; ++j) {
                float4 f = s_q4[q * NJ + j];
                num = fmaf(f.x, s2[j], num);
                num = fmaf(-f.y, px[j], num);
                num = fmaf(-f.z, py[j], num);
            }
            float val = __fdividef(num, s_den[q] + 1e-8f);
            if (q >= np_r) val = 100000.0f;
            if (val < best) { best = val; mm = q; }
        }

        // ---- scores (float2 matched-keypoint loads) ----
        const int mbase = mm * NJ;
        #pragma unroll
        for (int j = 0; j < NJ; ++j) {
            float2 mp = *(const float2*)&s_pr[2 * (mbase + j)];
            float mv = s_vr[mbase + j];
            float dx = px[j] - mp.x, dy = py[j] - mp.y;
            float score = __expf(-fsqrt_ap(dx * dx + dy * dy + 1e-12f) * 0.01f);
            float inb = (px[j] >= 0.0f && py[j] >= 0.0f &&
                         px[j] <= s_wh[0] - 1.0f && py[j] <= s_wh[1] - 1.0f) ? 1.0f : 0.0f;
            float bnd = inb * mv;
            sc[j] += score * bnd;
            bd[j] += bnd;
        }

        // ---- bone scores (hardcoded table; px/py register-resident) ----
        const float b20 = s_vr[mbase + 0];
        #pragma unroll
        for (int e = 0; e < NBONES; ++e) {
            const int a = ba[e], bb = bbt[e];
            float dxp = px[a] - px[bb], dyp = py[a] - py[bb];
            float blp = fsqrt_ap(dxp * dxp + dyp * dyp + 1e-12f);
            float2 ma = *(const float2*)&s_pr[2 * (mbase + a)];
            float2 mb = *(const float2*)&s_pr[2 * (mbase + bb)];
            float dxm = ma.x - mb.x, dym = ma.y - mb.y;
            float blm = fsqrt_ap(dxm * dxm + dym * dym + 1e-12f);
            float sbl = __expf(-fabsf(blm - blp) * 0.2f);
            sc2[e] += sbl * b20;
            bd2[e] += b20;
        }
    }

    float* xrow = g_xin + (size_t)n * PLANE;
    #pragma unroll
    for (int j = 0; j < NJ; ++j)
        xrow[j * ND + d] = sc[j] / (bd[j] + 1e-8f);
    #pragma unroll
    for (int e = 0; e < NBONES; ++e)
        xrow[(NJ + e) * ND + d] = sc2[e] / (bd2[e] + 1e-8f);
}

// ---------------------------------------------------------------------------
// Kernel C: conv1 bf16-split GEMM (mma.sync, 2 CTA/SM) + SHUFFLE-FREE fused
// conv2 (per-lane position accumulators, one deferred exchange) + softmax +
// masked expectation.  One block (256 thr, 8 warps) per n.
// y at u contributes w2->logit[u-1], w1->logit[u], w0->logit[u+1].
// Lane q owns u in {2q,2q+1,2q+8,2q+9}; accumulators L[0..3] cover positions
// 2q-1..2q+2, L[4..7] cover 2q+7..2q+10 (local to the warp's 16-t window).
// ---------------------------------------------------------------------------
__global__ __launch_bounds__(256, 2) void k_conv_tc(
    const float* __restrict__ bc2, float* __restrict__ out)
{
    extern __shared__ __align__(16) unsigned char smem_raw[];
    __shared__ float s_part[8][4][8];
    __shared__ float s_logit[ND];
    __shared__ float s_red[ND];

    const int n   = blockIdx.x;
    const int tid = threadIdx.x;
    const int w    = tid >> 5;
    const int lane = tid & 31;
    const int g = lane >> 2, q = lane & 3;
    (void)q;

    const uint32_t sbase = smem_u32(smem_raw);
    const uint32_t xhi = sbase;
    const uint32_t xlo = sbase + XBYTES;

    // ---- build im2col X (t-major, bf16 hi/lo k-pairs) ----
    {
        const float* src = g_xin + (size_t)n * PLANE;
        for (int idx = tid; idx < 128 * 64; idx += 256) {
            const int kp = idx & 63;
            if (kp >= 56) continue;
            const int t = idx >> 6;
            const int k0 = 2 * kp;
            float v0 = 0.0f, v1 = 0.0f;
            if (k0 < 99) {
                int c = k0 / 3, tap = k0 - 3 * c;
                int tt = t + tap - 1;
                if (tt >= 0 && tt < ND) v0 = src[c * ND + tt];
            }
            if (k0 + 1 < 99) {
                int c = (k0 + 1) / 3, tap = (k0 + 1) - 3 * c;
                int tt = t + tap - 1;
                if (tt >= 0 && tt < ND) v1 = src[c * ND + tt];
            }
            uint32_t hi, lo;
            split_pack(v0, v1, hi, lo);
            const uint32_t off = (uint32_t)t * XROW + (uint32_t)kp * 4;
            asm volatile("st.shared.b32 [%0], %1;" :: "r"(xhi + off), "r"(hi) : "memory");
            asm volatile("st.shared.b32 [%0], %1;" :: "r"(xlo + off), "r"(lo) : "memory");
        }
    }
    __syncthreads();   // X visible

    // ---- load resident B fragments (all 7 k-steps for this warp's 16 t) ----
    uint32_t bh[NKS][4], bl[NKS][4];
    {
        const int seg = lane >> 3, rs = lane & 7;
        const int t = 16 * w + ((seg & 2) << 2) + rs;   // +8 rows for seg 2,3
        const uint32_t kbyte = (uint32_t)(seg & 1) * 16u;
        #pragma unroll
        for (int ks = 0; ks < NKS; ++ks) {
            const uint32_t a = xhi + (uint32_t)t * XROW + (uint32_t)ks * 32 + kbyte;
            ldsm4(bh[ks], a);
            ldsm4(bl[ks], a + XBYTES);
        }
    }
    __syncthreads();   // all ldsm done -> X region reusable as A ring

    // ---- prologue: chunks 0,1,2 into ring slots 0,1,2 ----
    #pragma unroll
    for (int c = 0; c < 3; ++c) {
        const unsigned char* gsrc = g_Wst + (size_t)c * ACHUNK;
        const uint32_t dst = sbase + (uint32_t)(c * ACHUNK);
        for (int i = tid; i < ACHUNK / 16; i += 256) cp16(dst + i * 16, gsrc + i * 16);
        cp_commit();
    }

    float L[8];
    #pragma unroll
    for (int i = 0; i < 8; ++i) L[i] = 0.0f;

    #pragma unroll 1
    for (int mt = 0; mt < NMT; ++mt) {
        if (mt < NMT - 2) cp_wait2();
        else if (mt == NMT - 2) cp_wait1();
        else cp_wait0();
        __syncthreads();   // chunk mt resident; slot (mt+3)&3 readers done

        if (mt + 3 < NMT) {
            const unsigned char* gsrc = g_Wst + (size_t)(mt + 3) * ACHUNK;
            const uint32_t dst = sbase + (uint32_t)(((mt + 3) & 3) * ACHUNK);
            for (int i = tid; i < ACHUNK / 16; i += 256) cp16(dst + i * 16, gsrc + i * 16);
            cp_commit();
        }

        const uint4* sA = (const uint4*)(smem_raw + (mt & 3) * ACHUNK);

        float acc0[2][4], acc1[2][4];
        #pragma unroll
        for (int nt = 0; nt < 2; ++nt)
            #pragma unroll
            for (int j = 0; j < 4; ++j) { acc0[nt][j] = 0.0f; acc1[nt][j] = 0.0f; }

        #pragma unroll
        for (int ks = 0; ks < NKS; ++ks) {
            const uint4 h0 = sA[(ks * 4 + 0) * 32 + lane];
            const uint4 h1 = sA[(ks * 4 + 1) * 32 + lane];
            const uint4 l0 = sA[(ks * 4 + 2) * 32 + lane];
            const uint4 l1 = sA[(ks * 4 + 3) * 32 + lane];
            #pragma unroll
            for (int nt = 0; nt < 2; ++nt) {
                const uint32_t b0h = bh[ks][2 * nt], b1h = bh[ks][2 * nt + 1];
                const uint32_t b0l = bl[ks][2 * nt], b1l = bl[ks][2 * nt + 1];
                mma_bf16(acc0[nt], h0.x, h0.y, h0.z, h0.w, b0h, b1h);
                mma_bf16(acc0[nt], h0.x, h0.y, h0.z, h0.w, b0l, b1l);
                mma_bf16(acc0[nt], l0.x, l0.y, l0.z, l0.w, b0h, b1h);
                mma_bf16(acc1[nt], h1.x, h1.y, h1.z, h1.w, b0h, b1h);
                mma_bf16(acc1[nt], h1.x, h1.y, h1.z, h1.w, b0l, b1l);
                mma_bf16(acc1[nt], l1.x, l1.y, l1.z, l1.w, b0h, b1h);
            }
        }

        // ---- shuffle-free conv2 epilogue: scatter into position accums ----
        const float4* meta = (const float4*)(smem_raw + (mt & 3) * ACHUNK + AFRAG);
        #pragma unroll
        for (int r = 0; r < 4; ++r) {
            const float4 m = meta[g + 8 * r];
            float ya, yb, yc, yd;
            if (r == 0)      { ya = acc0[0][0]; yb = acc0[0][1]; yc = acc0[1][0]; yd = acc0[1][1]; }
            else if (r == 1) { ya = acc0[0][2]; yb = acc0[0][3]; yc = acc0[1][2]; yd = acc0[1][3]; }
            else if (r == 2) { ya = acc1[0][0]; yb = acc1[0][1]; yc = acc1[1][0]; yd = acc1[1][1]; }
            else             { ya = acc1[0][2]; yb = acc1[0][3]; yc = acc1[1][2]; yd = acc1[1][3]; }
            ya = fmaxf(ya + m.x, 0.0f);
            yb = fmaxf(yb + m.x, 0.0f);
            yc = fmaxf(yc + m.x, 0.0f);
            yd = fmaxf(yd + m.x, 0.0f);
            const float w0 = m.y, w1 = m.z, w2 = m.w;

            L[0] = fmaf(w2, ya, L[0]);                       // pos 2q-1
            L[1] = fmaf(w1, ya, fmaf(w2, yb, L[1]));         // pos 2q
            L[2] = fmaf(w0, ya, fmaf(w1, yb, L[2]));         // pos 2q+1
            L[3] = fmaf(w0, yb, L[3]);                       // pos 2q+2
            L[4] = fmaf(w2, yc, L[4]);                       // pos 2q+7
            L[5] = fmaf(w1, yc, fmaf(w2, yd, L[5]));         // pos 2q+8
            L[6] = fmaf(w0, yc, fmaf(w1, yd, L[6]));         // pos 2q+9
            L[7] = fmaf(w0, yd, L[7]);                       // pos 2q+10
        }
    }

    // ---- one-time butterfly over g, then smem gather ----
    #pragma unroll
    for (int i = 0; i < 8; ++i) {
        #pragma unroll
        for (int off = 4; off <= 16; off <<= 1)
            L[i] += __shfl_xor_sync(0xffffffffu, L[i], off);
    }
    if (lane < 4) {
        #pragma unroll
        for (int i = 0; i < 8; ++i) s_part[w][lane][i] = L[i];
    }
    __syncthreads();

    if (tid < ND) {
        const int wt = tid >> 4, lt = tid & 15;
        float v = bc2[0];
        #pragma unroll
        for (int qq = 0; qq < 4; ++qq) {
            int s = lt + 1 - 2 * qq;            // groupA: pos 2q-1+s
            if (s >= 0 && s < 4) v += s_part[wt][qq][s];
            int s2 = lt - 7 - 2 * qq;           // groupB: pos 2q+7+s2
            if (s2 >= 0 && s2 < 4) v += s_part[wt][qq][4 + s2];
        }
        if (lt == 0  && wt > 0) v += s_part[wt - 1][3][7];   // left halo (pos 16)
        if (lt == 15 && wt < 7) v += s_part[wt + 1][0][0];   // right halo (pos -1)
        s_logit[tid] = v;
    }
    __syncthreads();

    // ---- softmax + argmax window + masked expectation ----
    if (tid < ND) s_red[tid] = s_logit[tid];
    __syncthreads();
    for (int s = 64; s > 0; s >>= 1) {
        if (tid < s) s_red[tid] = fmaxf(s_red[tid], s_red[tid + s]);
        __syncthreads();
    }
    const float mx = s_red[0];
    __syncthreads();

    if (tid < ND) s_red[tid] = (s_logit[tid] == mx) ? (float)tid : 1.0e9f;
    __syncthreads();
    for (int s = 64; s > 0; s >>= 1) {
        if (tid < s) s_red[tid] = fminf(s_red[tid], s_red[tid + s]);
        __syncthreads();
    }
    const int idx = (int)s_red[0];
    __syncthreads();

    float e = 0.0f;
    if (tid < ND) e = expf(s_logit[tid] - mx);

    if (tid < ND) s_red[tid] = e;
    __syncthreads();
    for (int s = 64; s > 0; s >>= 1) {
        if (tid < s) s_red[tid] += s_red[tid + s];
        __syncthreads();
    }
    const float S = s_red[0];
    __syncthreads();

    const float me = (tid < ND && abs(tid - idx) <= 5) ? e : 0.0f;

    if (tid < ND) s_red[tid] = me;
    __syncthreads();
    for (int s = 64; s > 0; s >>= 1) {
        if (tid < s) s_red[tid] += s_red[tid + s];
        __syncthreads();
    }
    const float den = s_red[0];
    __syncthreads();

    if (tid < ND) s_red[tid] = me * (float)tid;
    __syncthreads();
    for (int s = 64; s > 0; s >>= 1) {
        if (tid < s) s_red[tid] += s_red[tid + s];
        __syncthreads();
    }
    if (tid == 0) {
        float pred = s_red[0] / (den + 1e-8f * S);
        out[n] = pred * (6000.0f / 127.0f) + 2000.0f;
    }
}

// ---------------------------------------------------------------------------
extern "C" void kernel_launch(void* const* d_in, const int* in_sizes, int n_in,
                              void* d_out, int out_size)
{
    const float* kpts        = (const float*)d_in[0];
    const float* joint_vis   = (const float*)d_in[2];
    const float* cam_R       = (const float*)d_in[5];
    const float* cam_T       = (const float*)d_in[6];
    const float* cam_f       = (const float*)d_in[7];
    const float* cam_c       = (const float*)d_in[8];
    const float* image_wh    = (const float*)d_in[9];
    const int*   num_persons = (const int*)d_in[10];
    const float* Wr1         = (const float*)d_in[11];
    const float* br1         = (const float*)d_in[12];
    const float* Wr2         = (const float*)d_in[13];
    const float* br2         = (const float*)d_in[14];
    const float* Wc1         = (const float*)d_in[15];
    const float* bc1         = (const float*)d_in[16];
    const float* Wc2         = (const float*)d_in[17];
    const float* bc2         = (const float*)d_in[18];
    float* out = (float*)d_out;

    cudaFuncSetAttribute(k_conv_tc, cudaFuncAttributeMaxDynamicSharedMemorySize,
                         SMEM_DYN);

    k_repack_frag<<<NMT, 256>>>(Wc1, bc1, Wc2);
    k_match<<<NROWS, 128>>>(kpts, joint_vis, cam_R, cam_T, cam_f, cam_c,
                            image_wh, num_persons, Wr1, br1, Wr2, br2);
    k_conv_tc<<<NROWS, 256, SMEM_DYN>>>(bc2, out);
}

// round 15
// speedup vs baseline: 1.2447x; 1.0288x over previous
#include <cuda_runtime.h>
#include <cuda_bf16.h>
#include <cstdint>
#include <math.h>

// Problem constants
#define NV 5
#define NB_ 32      // batch
#define NP 20
#define NJ 17
#define NBONES 16
#define ND 128
#define HR 1024
#define HID 1024
#define NROWS (NB_*NP)          // 640
#define NC (NJ + NBONES)        // 33
#define NKS 7                   // k-steps of 16 (K=112)
#define NMT 32                  // m-steps of 32 h (full)
#define NMT_H 16                // per half-block
#define XROW 240                // X row stride in bytes (56 kpairs = 224B + pad)
#define XBYTES (128 * XROW)     // 30720
#define AFRAG  (NKS * 4 * 32 * 16)          // 14336
#define ACHUNK (AFRAG + 32 * 16)            // + meta {bc1,w0,w1,w2} = 14848
#define SMEM_DYN (2 * XBYTES)               // 61440; A ring (4*ACHUNK) reuses it
#define PLANE (NC * ND)                     // 4224

// Scratch (device globals; no runtime allocation)
__device__ float g_xin[NROWS * PLANE];                       // (n, c, t)
__device__ float g_plog[2 * NROWS * ND];                     // half partial logits
__device__ __align__(16) unsigned char g_Wst[NMT * ACHUNK];  // A frags + meta

// ---------------------------------------------------------------------------
// helpers
// ---------------------------------------------------------------------------
__device__ __forceinline__ void split_pack(float v0, float v1, uint32_t& hi, uint32_t& lo) {
    __nv_bfloat16 h0 = __float2bfloat16(v0);
    __nv_bfloat16 h1 = __float2bfloat16(v1);
    float r0 = v0 - __bfloat162float(h0);
    float r1 = v1 - __bfloat162float(h1);
    __nv_bfloat16 l0 = __float2bfloat16(r0);
    __nv_bfloat16 l1 = __float2bfloat16(r1);
    hi = ((uint32_t)__bfloat16_as_ushort(h1) << 16) | (uint32_t)__bfloat16_as_ushort(h0);
    lo = ((uint32_t)__bfloat16_as_ushort(l1) << 16) | (uint32_t)__bfloat16_as_ushort(l0);
}

__device__ __forceinline__ uint32_t smem_u32(const void* p) {
    uint32_t a;
    asm("{ .reg .u64 t; cvta.to.shared.u64 t, %1; cvt.u32.u64 %0, t; }" : "=r"(a) : "l"(p));
    return a;
}

__device__ __forceinline__ void mma_bf16(float* c,
                                         uint32_t a0, uint32_t a1, uint32_t a2, uint32_t a3,
                                         uint32_t b0, uint32_t b1) {
    asm volatile("mma.sync.aligned.m16n8k16.row.col.f32.bf16.bf16.f32 "
                 "{%0,%1,%2,%3},{%4,%5,%6,%7},{%8,%9},{%0,%1,%2,%3};"
                 : "+f"(c[0]), "+f"(c[1]), "+f"(c[2]), "+f"(c[3])
                 : "r"(a0), "r"(a1), "r"(a2), "r"(a3), "r"(b0), "r"(b1));
}

__device__ __forceinline__ void ldsm4(uint32_t* r, uint32_t addr) {
    asm volatile("ldmatrix.sync.aligned.m8n8.x4.shared.b16 {%0,%1,%2,%3}, [%4];"
                 : "=r"(r[0]), "=r"(r[1]), "=r"(r[2]), "=r"(r[3]) : "r"(addr));
}

__device__ __forceinline__ void cp16(uint32_t s, const void* g) {
    asm volatile("cp.async.cg.shared.global [%0], [%1], 16;" :: "r"(s), "l"(g));
}
__device__ __forceinline__ void cp_commit() { asm volatile("cp.async.commit_group;" ::: "memory"); }
__device__ __forceinline__ void cp_wait2()  { asm volatile("cp.async.wait_group 2;" ::: "memory"); }
__device__ __forceinline__ void cp_wait1()  { asm volatile("cp.async.wait_group 1;" ::: "memory"); }
__device__ __forceinline__ void cp_wait0()  { asm volatile("cp.async.wait_group 0;" ::: "memory"); }

__device__ __forceinline__ float fsqrt_ap(float x) {
    float r; asm("sqrt.approx.f32 %0, %1;" : "=f"(r) : "f"(x)); return r;
}

// ---------------------------------------------------------------------------
// Kernel W: pack conv1 weights into per-mt A-fragment chunks + meta.
// ---------------------------------------------------------------------------
__global__ __launch_bounds__(256) void k_repack_frag(
    const float* __restrict__ Wc1, const float* __restrict__ bc1,
    const float* __restrict__ Wc2)
{
    const int mt  = blockIdx.x;
    const int tid = threadIdx.x;
    unsigned char* chunk = g_Wst + (size_t)mt * ACHUNK;

    if (tid < 224) {
        const int ks = tid >> 5, lane = tid & 31;
        const int g = lane >> 2, q = lane & 3;
        const int k0 = ks * 16 + 2 * q;
        #pragma unroll
        for (int tile = 0; tile < 2; ++tile) {
            const int hA = mt * 32 + tile * 16 + g;
            const int hB = hA + 8;
            const int hh[4] = {hA, hB, hA, hB};
            const int kk[4] = {k0, k0, k0 + 8, k0 + 8};
            float v[8];
            #pragma unroll
            for (int r = 0; r < 4; ++r) {
                v[2*r]   = (kk[r]     < 99) ? Wc1[hh[r] * 99 + kk[r]]     : 0.0f;
                v[2*r+1] = (kk[r] + 1 < 99) ? Wc1[hh[r] * 99 + kk[r] + 1] : 0.0f;
            }
            uint32_t hi[4], lo[4];
            #pragma unroll
            for (int r = 0; r < 4; ++r) split_pack(v[2*r], v[2*r+1], hi[r], lo[r]);
            *(uint4*)(chunk + (((ks * 4 + 0 + tile) * 32) + lane) * 16) =
                make_uint4(hi[0], hi[1], hi[2], hi[3]);
            *(uint4*)(chunk + (((ks * 4 + 2 + tile) * 32) + lane) * 16) =
                make_uint4(lo[0], lo[1], lo[2], lo[3]);
        }
    } else {
        const int hl = tid - 224;
        const int h = mt * 32 + hl;
        *(float4*)(chunk + AFRAG + hl * 16) =
            make_float4(bc1[h], Wc2[h * 3], Wc2[h * 3 + 1], Wc2[h * 3 + 2]);
    }
}

// ---------------------------------------------------------------------------
// Kernel B: rough MLP + projection + matching + scores (all fused).
// One block per (b,p); thread = depth bin d.  (R13 + bd bit-packing,
// bd2 collapsed to per-view scalar — bit-exact, ~30 fewer live registers.)
// ---------------------------------------------------------------------------
__global__ __launch_bounds__(128) void k_match(
    const float* __restrict__ kpts, const float* __restrict__ joint_vis,
    const float* __restrict__ cam_R, const float* __restrict__ cam_T,
    const float* __restrict__ cam_f, const float* __restrict__ cam_c,
    const float* __restrict__ image_wh, const int* __restrict__ num_persons,
    const float* __restrict__ Wr1, const float* __restrict__ br1,
    const float* __restrict__ Wr2, const float* __restrict__ br2)
{
    __shared__ float xs[NJ * 2];
    __shared__ float hs[HR];
    __shared__ float s_rough[NJ];
    __shared__ __align__(8) float s_uvn[NJ * 2];
    __shared__ float s_R0[9], s_T0[3];
    __shared__ __align__(8) float s_pr[NP * NJ * 2];
    __shared__ float s_vr[NP * NJ];
    __shared__ float s_Rr[9], s_Tr[3], s_fr[2], s_cr[2], s_wh[2];
    __shared__ float4 s_q4[NP * NJ];
    __shared__ float s_base[NP], s_den[NP];

    const int n = blockIdx.x;
    const int b = n / NP, p = n % NP;
    const int d = threadIdx.x;

    // ---- static loads + rough-MLP input ----
    if (d < NJ * 2)
        xs[d] = kpts[(((0 * NB_ + b) * NP + p) * NJ) * 2 + d] / image_wh[d & 1];
    if (d < 9)  s_R0[d] = cam_R[(0 * NB_ + b) * 9 + d];
    if (d < 3)  s_T0[d] = cam_T[(0 * NB_ + b) * 3 + d];
    if (d >= 64 && d < 64 + NJ * 2) {
        int m = d - 64;
        int c = m & 1;
        float cc = cam_c[(0 * NB_ + b) * 2 + c];
        float ff = cam_f[(0 * NB_ + b) * 2 + c];
        s_uvn[m] = (kpts[(((0 * NB_ + b) * NP + p) * NJ) * 2 + m] - cc) / ff;
    }
    __syncthreads();

    // ---- rough MLP (fused) ----
    for (int i = d; i < HR; i += 128) {
        const float* wr = Wr1 + i * (NJ * 2);
        float acc = br1[i];
        #pragma unroll
        for (int m = 0; m < NJ * 2; ++m) acc += wr[m] * xs[m];
        hs[i] = fmaxf(acc, 0.0f);
    }
    __syncthreads();
    {
        const int warp = d >> 5, lane = d & 31;
        for (int j = warp; j < NJ; j += 4) {
            const float* wr = Wr2 + j * HR;
            float acc = 0.0f;
            for (int i = lane; i < HR; i += 32) acc += hs[i] * wr[i];
            #pragma unroll
            for (int off = 16; off > 0; off >>= 1)
                acc += __shfl_down_sync(0xffffffffu, acc, off);
            if (lane == 0) s_rough[j] = (acc + br2[j]) * 1000.0f;
        }
    }

    float sc[NJ], sc2[NBONES];
    uint32_t bdp0 = 0u, bdp1 = 0u;   // bd[j]: 3-bit counters (j<10 | j>=10)
    float bd2s = 0.0f;               // bd2 (e-invariant)
    #pragma unroll
    for (int j = 0; j < NJ; ++j) sc[j] = 0.0f;
    #pragma unroll
    for (int e = 0; e < NBONES; ++e) sc2[e] = 0.0f;

    const float label = ((float)d / 127.0f) * 6000.0f + 2000.0f;
    const int ba[NBONES]  = {0,0,1,2,5,5,7,6,8,5,6,11,11,13,12,14};
    const int bbt[NBONES] = {1,2,3,4,6,7,9,8,10,11,12,12,13,15,14,16};

    for (int rv = 1; rv < NV; ++rv) {
        __syncthreads();
        const int cambase = rv * NB_ + b;
        {
            const float* src = kpts + (size_t)cambase * NP * NJ * 2;
            for (int idx = d; idx < NP * NJ * 2; idx += 128) s_pr[idx] = src[idx];
            const float* vsrc = joint_vis + (size_t)cambase * NP * NJ;
            for (int idx = d; idx < NP * NJ; idx += 128) s_vr[idx] = vsrc[idx];
            if (d < 9) s_Rr[d] = cam_R[cambase * 9 + d];
            if (d < 3) s_Tr[d] = cam_T[cambase * 3 + d];
            if (d < 2) {
                s_fr[d] = cam_f[cambase * 2 + d];
                s_cr[d] = cam_c[cambase * 2 + d];
                s_wh[d] = image_wh[cambase * 2 + d];
            }
        }
        __syncthreads();
        // per-view precompute for expanded-distance argmin
        for (int idx = d; idx < NP * NJ; idx += 128) {
            float w   = s_vr[idx];
            float2 pr = *(const float2*)&s_pr[2 * idx];
            s_q4[idx] = make_float4(w, 2.0f * w * pr.x, 2.0f * w * pr.y,
                                    w * (pr.x * pr.x + pr.y * pr.y));
        }
        __syncthreads();
        if (d < NP) {
            float bs = 0.0f, dn = 0.0f;
            #pragma unroll
            for (int j = 0; j < NJ; ++j) {
                bs += s_q4[d * NJ + j].w;
                dn += s_q4[d * NJ + j].x;
            }
            s_base[d] = bs; s_den[d] = dn;
        }
        __syncthreads();
        const int np_r = num_persons[rv * NB_ + b];

        // ---- projection ----
        float px[NJ], py[NJ], s2[NJ];
        #pragma unroll
        for (int j = 0; j < NJ; ++j) {
            float z  = label + s_rough[j];
            float2 uv = *(const float2*)&s_uvn[2 * j];
            float cx = uv.x * z;
            float cy = uv.y * z;
            float p0 = s_R0[0] * cx + s_R0[3] * cy + s_R0[6] * z + s_T0[0];
            float p1 = s_R0[1] * cx + s_R0[4] * cy + s_R0[7] * z + s_T0[1];
            float p2 = s_R0[2] * cx + s_R0[5] * cy + s_R0[8] * z + s_T0[2];
            float q0 = p0 - s_Tr[0], q1 = p1 - s_Tr[1], q2 = p2 - s_Tr[2];
            float xc0 = s_Rr[0] * q0 + s_Rr[1] * q1 + s_Rr[2] * q2;
            float xc1 = s_Rr[3] * q0 + s_Rr[4] * q1 + s_Rr[5] * q2;
            float xc2 = s_Rr[6] * q0 + s_Rr[7] * q1 + s_Rr[8] * q2;
            float inv = 1.0f / (xc2 + 1e-8f);
            px[j] = xc0 * inv * s_fr[0] + s_cr[0];
            py[j] = xc1 * inv * s_fr[1] + s_cr[1];
            s2[j] = px[j] * px[j] + py[j] * py[j];
        }

        // ---- argmin via expanded distance (single accumulator) ----
        float best = 3.4e38f; int mm = 0;
        for (int q = 0; q < NP; ++q) {
            float num = s_base[q];
            #pragma unroll
            for (int j = 0; j < NJ; ++j) {
                float4 f = s_q4[q * NJ + j];
                num = fmaf(f.x, s2[j], num);
                num = fmaf(-f.y, px[j], num);
                num = fmaf(-f.z, py[j], num);
            }
            float val = __fdividef(num, s_den[q] + 1e-8f);
            if (q >= np_r) val = 100000.0f;
            if (val < best) { best = val; mm = q; }
        }

        // ---- scores (float2 matched-keypoint loads; bd as bit counters) ----
        const int mbase = mm * NJ;
        #pragma unroll
        for (int j = 0; j < NJ; ++j) {
            float2 mp = *(const float2*)&s_pr[2 * (mbase + j)];
            float mv = s_vr[mbase + j];
            float dx = px[j] - mp.x, dy = py[j] - mp.y;
            float score = __expf(-fsqrt_ap(dx * dx + dy * dy + 1e-12f) * 0.01f);
            bool inb = (px[j] >= 0.0f && py[j] >= 0.0f &&
                        px[j] <= s_wh[0] - 1.0f && py[j] <= s_wh[1] - 1.0f);
            uint32_t ib = (inb && mv != 0.0f) ? 1u : 0u;
            sc[j] += ib ? score : 0.0f;
            if (j < 10) bdp0 += ib << (3 * j);
            else        bdp1 += ib << (3 * (j - 10));
        }

        // ---- bone scores (hardcoded table; px/py register-resident) ----
        const float b20 = s_vr[mbase + 0];
        bd2s += b20;
        #pragma unroll
        for (int e = 0; e < NBONES; ++e) {
            const int a = ba[e], bb = bbt[e];
            float dxp = px[a] - px[bb], dyp = py[a] - py[bb];
            float blp = fsqrt_ap(dxp * dxp + dyp * dyp + 1e-12f);
            float2 ma = *(const float2*)&s_pr[2 * (mbase + a)];
            float2 mb = *(const float2*)&s_pr[2 * (mbase + bb)];
            float dxm = ma.x - mb.x, dym = ma.y - mb.y;
            float blm = fsqrt_ap(dxm * dxm + dym * dym + 1e-12f);
            float sbl = __expf(-fabsf(blm - blp) * 0.2f);
            sc2[e] += sbl * b20;
        }
    }

    float* xrow = g_xin + (size_t)n * PLANE;
    #pragma unroll
    for (int j = 0; j < NJ; ++j) {
        uint32_t c = (j < 10) ? ((bdp0 >> (3 * j)) & 7u) : ((bdp1 >> (3 * (j - 10))) & 7u);
        xrow[j * ND + d] = sc[j] / ((float)c + 1e-8f);
    }
    const float inv2 = 1.0f / (bd2s + 1e-8f);
    #pragma unroll
    for (int e = 0; e < NBONES; ++e)
        xrow[(NJ + e) * ND + d] = sc2[e] * inv2;
}

// ---------------------------------------------------------------------------
// Kernel C: conv1 bf16-split GEMM, h-split x2 (grid.y = half).  Each half
// does 16 m-steps, shuffle-free conv2 accumulation, writes 128 partial
// logits to g_plog.  (R14 core, halved.)
// ---------------------------------------------------------------------------
__global__ __launch_bounds__(256, 2) void k_conv_tc(float* __restrict__ plog)
{
    extern __shared__ __align__(16) unsigned char smem_raw[];
    __shared__ float s_part[8][4][8];

    const int n   = blockIdx.x;
    const int hb  = blockIdx.y;
    const int tid = threadIdx.x;
    const int w    = tid >> 5;
    const int lane = tid & 31;
    const int g = lane >> 2;

    const uint32_t sbase = smem_u32(smem_raw);
    const uint32_t xhi = sbase;
    const uint32_t xlo = sbase + XBYTES;

    // ---- build im2col X (t-major, bf16 hi/lo k-pairs) ----
    {
        const float* src = g_xin + (size_t)n * PLANE;
        for (int idx = tid; idx < 128 * 64; idx += 256) {
            const int kp = idx & 63;
            if (kp >= 56) continue;
            const int t = idx >> 6;
            const int k0 = 2 * kp;
            float v0 = 0.0f, v1 = 0.0f;
            if (k0 < 99) {
                int c = k0 / 3, tap = k0 - 3 * c;
                int tt = t + tap - 1;
                if (tt >= 0 && tt < ND) v0 = src[c * ND + tt];
            }
            if (k0 + 1 < 99) {
                int c = (k0 + 1) / 3, tap = (k0 + 1) - 3 * c;
                int tt = t + tap - 1;
                if (tt >= 0 && tt < ND) v1 = src[c * ND + tt];
            }
            uint32_t hi, lo;
            split_pack(v0, v1, hi, lo);
            const uint32_t off = (uint32_t)t * XROW + (uint32_t)kp * 4;
            asm volatile("st.shared.b32 [%0], %1;" :: "r"(xhi + off), "r"(hi) : "memory");
            asm volatile("st.shared.b32 [%0], %1;" :: "r"(xlo + off), "r"(lo) : "memory");
        }
    }
    __syncthreads();   // X visible

    // ---- load resident B fragments (all 7 k-steps for this warp's 16 t) ----
    uint32_t bh[NKS][4], bl[NKS][4];
    {
        const int seg = lane >> 3, rs = lane & 7;
        const int t = 16 * w + ((seg & 2) << 2) + rs;
        const uint32_t kbyte = (uint32_t)(seg & 1) * 16u;
        #pragma unroll
        for (int ks = 0; ks < NKS; ++ks) {
            const uint32_t a = xhi + (uint32_t)t * XROW + (uint32_t)ks * 32 + kbyte;
            ldsm4(bh[ks], a);
            ldsm4(bl[ks], a + XBYTES);
        }
    }
    __syncthreads();   // all ldsm done -> X region reusable as A ring

    const unsigned char* wbase = g_Wst + (size_t)hb * NMT_H * ACHUNK;

    // ---- prologue: local chunks 0,1,2 into ring slots 0,1,2 ----
    #pragma unroll
    for (int c = 0; c < 3; ++c) {
        const unsigned char* gsrc = wbase + (size_t)c * ACHUNK;
        const uint32_t dst = sbase + (uint32_t)(c * ACHUNK);
        for (int i = tid; i < ACHUNK / 16; i += 256) cp16(dst + i * 16, gsrc + i * 16);
        cp_commit();
    }

    float L[8];
    #pragma unroll
    for (int i = 0; i < 8; ++i) L[i] = 0.0f;

    #pragma unroll 1
    for (int mt = 0; mt < NMT_H; ++mt) {
        if (mt < NMT_H - 2) cp_wait2();
        else if (mt == NMT_H - 2) cp_wait1();
        else cp_wait0();
        __syncthreads();

        if (mt + 3 < NMT_H) {
            const unsigned char* gsrc = wbase + (size_t)(mt + 3) * ACHUNK;
            const uint32_t dst = sbase + (uint32_t)(((mt + 3) & 3) * ACHUNK);
            for (int i = tid; i < ACHUNK / 16; i += 256) cp16(dst + i * 16, gsrc + i * 16);
            cp_commit();
        }

        const uint4* sA = (const uint4*)(smem_raw + (mt & 3) * ACHUNK);

        float acc0[2][4], acc1[2][4];
        #pragma unroll
        for (int nt = 0; nt < 2; ++nt)
            #pragma unroll
            for (int j = 0; j < 4; ++j) { acc0[nt][j] = 0.0f; acc1[nt][j] = 0.0f; }

        #pragma unroll
        for (int ks = 0; ks < NKS; ++ks) {
            const uint4 h0 = sA[(ks * 4 + 0) * 32 + lane];
            const uint4 h1 = sA[(ks * 4 + 1) * 32 + lane];
            const uint4 l0 = sA[(ks * 4 + 2) * 32 + lane];
            const uint4 l1 = sA[(ks * 4 + 3) * 32 + lane];
            #pragma unroll
            for (int nt = 0; nt < 2; ++nt) {
                const uint32_t b0h = bh[ks][2 * nt], b1h = bh[ks][2 * nt + 1];
                const uint32_t b0l = bl[ks][2 * nt], b1l = bl[ks][2 * nt + 1];
                mma_bf16(acc0[nt], h0.x, h0.y, h0.z, h0.w, b0h, b1h);
                mma_bf16(acc0[nt], h0.x, h0.y, h0.z, h0.w, b0l, b1l);
                mma_bf16(acc0[nt], l0.x, l0.y, l0.z, l0.w, b0h, b1h);
                mma_bf16(acc1[nt], h1.x, h1.y, h1.z, h1.w, b0h, b1h);
                mma_bf16(acc1[nt], h1.x, h1.y, h1.z, h1.w, b0l, b1l);
                mma_bf16(acc1[nt], l1.x, l1.y, l1.z, l1.w, b0h, b1h);
            }
        }

        // ---- shuffle-free conv2 epilogue ----
        const float4* meta = (const float4*)(smem_raw + (mt & 3) * ACHUNK + AFRAG);
        #pragma unroll
        for (int r = 0; r < 4; ++r) {
            const float4 m = meta[g + 8 * r];
            float ya, yb, yc, yd;
            if (r == 0)      { ya = acc0[0][0]; yb = acc0[0][1]; yc = acc0[1][0]; yd = acc0[1][1]; }
            else if (r == 1) { ya = acc0[0][2]; yb = acc0[0][3]; yc = acc0[1][2]; yd = acc0[1][3]; }
            else if (r == 2) { ya = acc1[0][0]; yb = acc1[0][1]; yc = acc1[1][0]; yd = acc1[1][1]; }
            else             { ya = acc1[0][2]; yb = acc1[0][3]; yc = acc1[1][2]; yd = acc1[1][3]; }
            ya = fmaxf(ya + m.x, 0.0f);
            yb = fmaxf(yb + m.x, 0.0f);
            yc = fmaxf(yc + m.x, 0.0f);
            yd = fmaxf(yd + m.x, 0.0f);
            const float w0 = m.y, w1 = m.z, w2 = m.w;

            L[0] = fmaf(w2, ya, L[0]);
            L[1] = fmaf(w1, ya, fmaf(w2, yb, L[1]));
            L[2] = fmaf(w0, ya, fmaf(w1, yb, L[2]));
            L[3] = fmaf(w0, yb, L[3]);
            L[4] = fmaf(w2, yc, L[4]);
            L[5] = fmaf(w1, yc, fmaf(w2, yd, L[5]));
            L[6] = fmaf(w0, yc, fmaf(w1, yd, L[6]));
            L[7] = fmaf(w0, yd, L[7]);
        }
    }

    // ---- one-time butterfly over g, then smem gather, write partials ----
    #pragma unroll
    for (int i = 0; i < 8; ++i) {
        #pragma unroll
        for (int off = 4; off <= 16; off <<= 1)
            L[i] += __shfl_xor_sync(0xffffffffu, L[i], off);
    }
    if (lane < 4) {
        #pragma unroll
        for (int i = 0; i < 8; ++i) s_part[w][lane][i] = L[i];
    }
    __syncthreads();

    if (tid < ND) {
        const int wt = tid >> 4, lt = tid & 15;
        float v = 0.0f;
        #pragma unroll
        for (int qq = 0; qq < 4; ++qq) {
            int s = lt + 1 - 2 * qq;
            if (s >= 0 && s < 4) v += s_part[wt][qq][s];
            int s2 = lt - 7 - 2 * qq;
            if (s2 >= 0 && s2 < 4) v += s_part[wt][qq][4 + s2];
        }
        if (lt == 0  && wt > 0) v += s_part[wt - 1][3][7];
        if (lt == 15 && wt < 7) v += s_part[wt + 1][0][0];
        plog[((size_t)hb * NROWS + n) * ND + tid] = v;
    }
}

// ---------------------------------------------------------------------------
// Kernel S: combine half partial logits + softmax + masked expectation.
// ---------------------------------------------------------------------------
__global__ __launch_bounds__(128) void k_soft(
    const float* __restrict__ bc2, float* __restrict__ out)
{
    __shared__ float s_logit[ND];
    __shared__ float s_red[ND];
    const int n = blockIdx.x;
    const int tid = threadIdx.x;

    s_logit[tid] = g_plog[(size_t)n * ND + tid]
                 + g_plog[(size_t)(NROWS + n) * ND + tid] + bc2[0];
    __syncthreads();

    s_red[tid] = s_logit[tid];
    __syncthreads();
    for (int s = 64; s > 0; s >>= 1) {
        if (tid < s) s_red[tid] = fmaxf(s_red[tid], s_red[tid + s]);
        __syncthreads();
    }
    const float mx = s_red[0];
    __syncthreads();

    s_red[tid] = (s_logit[tid] == mx) ? (float)tid : 1.0e9f;
    __syncthreads();
    for (int s = 64; s > 0; s >>= 1) {
        if (tid < s) s_red[tid] = fminf(s_red[tid], s_red[tid + s]);
        __syncthreads();
    }
    const int idx = (int)s_red[0];
    __syncthreads();

    const float e = expf(s_logit[tid] - mx);

    s_red[tid] = e;
    __syncthreads();
    for (int s = 64; s > 0; s >>= 1) {
        if (tid < s) s_red[tid] += s_red[tid + s];
        __syncthreads();
    }
    const float S = s_red[0];
    __syncthreads();

    const float me = (abs(tid - idx) <= 5) ? e : 0.0f;

    s_red[tid] = me;
    __syncthreads();
    for (int s = 64; s > 0; s >>= 1) {
        if (tid < s) s_red[tid] += s_red[tid + s];
        __syncthreads();
    }
    const float den = s_red[0];
    __syncthreads();

    s_red[tid] = me * (float)tid;
    __syncthreads();
    for (int s = 64; s > 0; s >>= 1) {
        if (tid < s) s_red[tid] += s_red[tid + s];
        __syncthreads();
    }
    if (tid == 0) {
        float pred = s_red[0] / (den + 1e-8f * S);
        out[n] = pred * (6000.0f / 127.0f) + 2000.0f;
    }
}

// ---------------------------------------------------------------------------
extern "C" void kernel_launch(void* const* d_in, const int* in_sizes, int n_in,
                              void* d_out, int out_size)
{
    const float* kpts        = (const float*)d_in[0];
    const float* joint_vis   = (const float*)d_in[2];
    const float* cam_R       = (const float*)d_in[5];
    const float* cam_T       = (const float*)d_in[6];
    const float* cam_f       = (const float*)d_in[7];
    const float* cam_c       = (const float*)d_in[8];
    const float* image_wh    = (const float*)d_in[9];
    const int*   num_persons = (const int*)d_in[10];
    const float* Wr1         = (const float*)d_in[11];
    const float* br1         = (const float*)d_in[12];
    const float* Wr2         = (const float*)d_in[13];
    const float* br2         = (const float*)d_in[14];
    const float* Wc1         = (const float*)d_in[15];
    const float* bc1         = (const float*)d_in[16];
    const float* Wc2         = (const float*)d_in[17];
    const float* bc2         = (const float*)d_in[18];
    float* out = (float*)d_out;

    cudaFuncSetAttribute(k_conv_tc, cudaFuncAttributeMaxDynamicSharedMemorySize,
                         SMEM_DYN);

    float* plog;
    cudaGetSymbolAddress((void**)&plog, g_plog);

    k_repack_frag<<<NMT, 256>>>(Wc1, bc1, Wc2);
    k_match<<<NROWS, 128>>>(kpts, joint_vis, cam_R, cam_T, cam_f, cam_c,
                            image_wh, num_persons, Wr1, br1, Wr2, br2);
    k_conv_tc<<<dim3(NROWS, 2), 256, SMEM_DYN>>>(plog);
    k_soft<<<NROWS, 128>>>(bc2, out);
}